// round 4
// baseline (speedup 1.0000x reference)
#include <cuda_runtime.h>
#include <cuda_bf16.h>

#define SQ    256
#define BATCH 16
#define EMB   512
#define HID   256
#define HMD   128
#define G4    1024            // 4*HID
#define NROWS (SQ*BATCH)      // 4096
#define INW   512             // input width both layers (E = 2H = 512)
#define NSC   (BATCH*SQ*SQ)   // 1,048,576 scores

// ---------------- scratch (device globals; no allocations allowed) ----------
__device__ float g_xa[NROWS * EMB];                 // 8 MB
__device__ float g_xb[NROWS * EMB];                 // 8 MB
__device__ float g_xproj[2 * SQ * G4 * BATCH];      // 32 MB : [dir][t][gate(1024)][b]
__device__ float g_hbuf[2][2][BATCH * HID];         // [pingpong][dir][b*256+k]
__device__ float g_p[BATCH * SQ * HMD];             // 2 MB
__device__ float g_cq[BATCH * SQ * HMD];            // 2 MB
__device__ unsigned g_arrive[2][64];                // per-dir distributed barrier flags

// ---------------- f32x2 packed math ------------------------------------------
__device__ __forceinline__ unsigned long long ffma2(unsigned long long a,
                                                    unsigned long long b,
                                                    unsigned long long c) {
    unsigned long long d;
    asm("fma.rn.f32x2 %0, %1, %2, %3;" : "=l"(d) : "l"(a), "l"(b), "l"(c));
    return d;
}
__device__ __forceinline__ unsigned long long pack2(float x, float y) {
    unsigned long long d;
    asm("mov.b64 %0, {%1, %2};" : "=l"(d) : "f"(x), "f"(y));
    return d;
}
__device__ __forceinline__ float2 unpack2(unsigned long long v) {
    float2 r;
    asm("mov.b64 {%0, %1}, %2;" : "=f"(r.x), "=f"(r.y) : "l"(v));
    return r;
}

// ---------------- scalar math helpers ----------------------------------------
__device__ __forceinline__ float ftanh(float x) {
    x = fminf(fmaxf(x, -15.f), 15.f);
    float e = __expf(2.f * x);
    return 1.f - __fdividef(2.f, e + 1.f);
}
__device__ __forceinline__ float fsig(float x) {
    x = fminf(fmaxf(x, -30.f), 30.f);
    return __fdividef(1.f, 1.f + __expf(-x));
}

// ---------------- 1) embedding gather (+ barrier flag reset) -----------------
__global__ __launch_bounds__(128) void embed_kernel(const int* __restrict__ concepts,
                                                    const float* __restrict__ emb) {
    if (blockIdx.x == 0 && threadIdx.x < 128)
        __stcg(&g_arrive[threadIdx.x >> 6][threadIdx.x & 63], 0u);
    int row = blockIdx.x;                       // s*16 + b
    int tok = concepts[row];
    const float4* src = (const float4*)(emb + (size_t)tok * EMB);
    float4* dst = (float4*)(g_xa + (size_t)row * EMB);
    dst[threadIdx.x] = src[threadIdx.x];        // 128 * float4 = 512 floats
}

// ---------------- 2) input projection GEMM: [4096,512] x [2048,512]^T -------
// out: g_xproj[((dir*256 + s)*1024 + g)*16 + b]   (b fastest for recurrence)
__global__ __launch_bounds__(256) void inproj_kernel(int layer,
                                                     const float* __restrict__ W,
                                                     const float* __restrict__ bias) {
    const float* __restrict__ A = layer ? g_xb : g_xa;
    __shared__ __align__(16) float As[16][68];
    __shared__ __align__(16) float Bs[16][68];
    int m0 = blockIdx.y << 6;
    int n0 = blockIdx.x << 6;
    int tid = threadIdx.x;
    int tm = tid >> 4, tn = tid & 15;
    int lr = tid >> 2, lc = (tid & 3) << 2;

    unsigned long long accp[4][2];
#pragma unroll
    for (int i = 0; i < 4; i++) { accp[i][0] = 0ull; accp[i][1] = 0ull; }

    for (int k0 = 0; k0 < INW; k0 += 16) {
        float4 av = *(const float4*)&A[(size_t)(m0 + lr) * INW + k0 + lc];
        float4 bv = *(const float4*)&W[(size_t)(n0 + lr) * INW + k0 + lc];
        As[lc + 0][lr] = av.x; As[lc + 1][lr] = av.y; As[lc + 2][lr] = av.z; As[lc + 3][lr] = av.w;
        Bs[lc + 0][lr] = bv.x; Bs[lc + 1][lr] = bv.y; Bs[lc + 2][lr] = bv.z; Bs[lc + 3][lr] = bv.w;
        __syncthreads();
#pragma unroll
        for (int kk = 0; kk < 16; kk++) {
            float4 a4 = *(const float4*)&As[kk][tm << 2];
            ulonglong2 b2 = *(const ulonglong2*)&Bs[kk][tn << 2];
            unsigned long long ad0 = pack2(a4.x, a4.x);
            unsigned long long ad1 = pack2(a4.y, a4.y);
            unsigned long long ad2 = pack2(a4.z, a4.z);
            unsigned long long ad3 = pack2(a4.w, a4.w);
            accp[0][0] = ffma2(ad0, b2.x, accp[0][0]);
            accp[0][1] = ffma2(ad0, b2.y, accp[0][1]);
            accp[1][0] = ffma2(ad1, b2.x, accp[1][0]);
            accp[1][1] = ffma2(ad1, b2.y, accp[1][1]);
            accp[2][0] = ffma2(ad2, b2.x, accp[2][0]);
            accp[2][1] = ffma2(ad2, b2.y, accp[2][1]);
            accp[3][0] = ffma2(ad3, b2.x, accp[3][0]);
            accp[3][1] = ffma2(ad3, b2.y, accp[3][1]);
        }
        __syncthreads();
    }
#pragma unroll
    for (int i = 0; i < 4; i++) {
        int m = m0 + (tm << 2) + i;
        int s = m >> 4, b = m & 15;
        float2 u0 = unpack2(accp[i][0]);
        float2 u1 = unpack2(accp[i][1]);
        float vals[4] = {u0.x, u0.y, u1.x, u1.y};
#pragma unroll
        for (int j = 0; j < 4; j++) {
            int n = n0 + (tn << 2) + j;
            int d = n >> 10, g = n & 1023;
            g_xproj[(size_t)((((d << 8) | s) << 10) | g) * BATCH + b] = vals[j] + bias[n];
        }
    }
}

// ---------------- 3) LSTM recurrence (persistent, 128 blocks, 256 thr) ------
// 64 CTAs/dir, each owns 4 hidden units (16 gate rows x 16 batch).
// Weights resident in REGISTERS (64 floats/thread, packed as 32 ull k-pairs).
// Thread = (ks 0..15, rg 0..3, bg 0..3): 4 rows x 4 batches x 16-k slice.
// h read straight from L2 (16 LDG.128/thread); only reduction uses smem.
__global__ __launch_bounds__(256) void lstm_rec_kernel(int layer,
                                                       const float* __restrict__ whh) {
    float* __restrict__ xout = layer ? g_xa : g_xb;
    int dir = blockIdx.x >> 6;
    int gb  = blockIdx.x & 63;
    int j0  = gb << 2;                 // 4 hidden units per CTA
    int tid = threadIdx.x;
    int ks = tid >> 4;                 // k-slice 0..15 (k = ks*16 .. +15)
    int rg = (tid >> 2) & 3;           // = gate index q for rows rg*4+i (u=i)
    int bg = tid & 3;                  // batch group (b = bg*4+j)

    __shared__ float part_s[16][16][20];   // [ks][r][b(+pad)]
    __shared__ float gate_s[16][17];       // [r][b]

    // ---- load weights into registers, packed as k-pairs --------------------
    // row r = rg*4 + i  ->  q = rg, u = i ; global row = dir*1024 + rg*256 + j0 + i
    unsigned long long w_ull[4][8];
#pragma unroll
    for (int i = 0; i < 4; i++) {
        const float* wr = whh + (size_t)((dir << 10) + (rg << 8) + j0 + i) * HID + (ks << 4);
#pragma unroll
        for (int m = 0; m < 4; m++) {
            float4 f = *(const float4*)&wr[m << 2];
            w_ull[i][m * 2]     = pack2(f.x, f.y);
            w_ull[i][m * 2 + 1] = pack2(f.z, f.w);
        }
    }
    if (tid < 64) {
        int b = tid & 15, u = tid >> 4;
        __stcg(&g_hbuf[0][dir][(b << 8) + j0 + u], 0.f);
    }
    float c_reg = 0.f;

    unsigned base = (unsigned)layer * 300u;
#define DIR_BARRIER(TARGET)                                                     \
    do {                                                                        \
        unsigned _tg = (TARGET);                                                \
        __syncthreads();                                                        \
        if (tid == 0) { __stcg(&g_arrive[dir][gb], _tg); }                      \
        for (;;) {                                                              \
            int ok = (tid < 64) ? (__ldcg(&g_arrive[dir][tid]) >= _tg) : 1;     \
            if (__syncthreads_count(ok) == 256) break;                          \
        }                                                                       \
        __threadfence();                                                        \
    } while (0)

    __threadfence();
    DIR_BARRIER(base + 1u);            // h(0) visible everywhere

    // readback thread mapping: tid -> (r = tid>>4, b = tid&15)
    int rb_r = tid >> 4, rb_b = tid & 15;
    int rb_q = rb_r >> 2, rb_u = rb_r & 3;
    int rb_off = (dir << 22) + ((rb_q << 8) + j0 + rb_u) * BATCH + rb_b;

    for (int p = 0; p < SQ; p++) {
        int t = dir ? (SQ - 1 - p) : p;
        const float* hsrc = g_hbuf[p & 1][dir] + (ks << 4);

        unsigned long long acc[4][4];
#pragma unroll
        for (int i = 0; i < 4; i++)
#pragma unroll
            for (int j = 0; j < 4; j++) acc[i][j] = 0ull;

#pragma unroll
        for (int j = 0; j < 4; j++) {
            const float* hb = hsrc + (((bg << 2) + j) << 8);
#pragma unroll
            for (int m = 0; m < 4; m++) {
                float4 h4 = *(const float4*)&hb[m << 2];
                unsigned long long h01 = pack2(h4.x, h4.y);
                unsigned long long h23 = pack2(h4.z, h4.w);
#pragma unroll
                for (int i = 0; i < 4; i++) {
                    acc[i][j] = ffma2(w_ull[i][m * 2],     h01, acc[i][j]);
                    acc[i][j] = ffma2(w_ull[i][m * 2 + 1], h23, acc[i][j]);
                }
            }
        }
        // prefetch xproj for the readback phase (independent of h)
        float xp = __ldg(&g_xproj[rb_off + (t << 14)]);

        // ---- write partials ------------------------------------------------
#pragma unroll
        for (int i = 0; i < 4; i++) {
            float2 p0 = unpack2(acc[i][0]);
            float2 p1 = unpack2(acc[i][1]);
            float2 p2 = unpack2(acc[i][2]);
            float2 p3 = unpack2(acc[i][3]);
            float4 v = make_float4(p0.x + p0.y, p1.x + p1.y, p2.x + p2.y, p3.x + p3.y);
            *(float4*)&part_s[ks][(rg << 2) + i][bg << 2] = v;
        }
        __syncthreads();

        // ---- reduce over 16 k-slices; thread (r,b) owns one gate -----------
        float gsum = xp;
#pragma unroll
        for (int s2 = 0; s2 < 16; s2++) gsum += part_s[s2][rb_r][rb_b];
        gate_s[rb_r][rb_b] = gsum;
        __syncthreads();

        if (tid < 64) {
            int b = tid & 15, u = tid >> 4;
            float gi = gate_s[u][b];
            float gf = gate_s[4 + u][b];
            float gg = gate_s[8 + u][b];
            float go = gate_s[12 + u][b];
            c_reg = fsig(gf) * c_reg + fsig(gi) * ftanh(gg);
            float h = fsig(go) * ftanh(c_reg);
            __stcg(&g_hbuf[(p + 1) & 1][dir][(b << 8) + j0 + u], h);
            xout[(size_t)((t * BATCH + b) << 9) + (dir << 8) + j0 + u] = h;
            __threadfence();
        }
        DIR_BARRIER(base + 2u + (unsigned)p);
    }
#undef DIR_BARRIER
}

// ---------------- 4) attention projections ----------------------------------
// n0 in {0,64} -> Ua -> g_p[(b*256+s)*128+n] ; n0 in {128,192} -> Wa -> g_cq
__global__ __launch_bounds__(256) void attnproj_kernel(const float* __restrict__ Ua,
                                                       const float* __restrict__ Wa) {
    const float* __restrict__ A = g_xa;   // layer-1 output [s][b][512]
    __shared__ __align__(16) float As[16][68];
    __shared__ __align__(16) float Bs[16][68];
    int m0 = blockIdx.y << 6;
    int n0 = blockIdx.x << 6;
    const float* Wsel = (n0 < 128) ? Ua : Wa;
    int nbase = (n0 < 128) ? n0 : (n0 - 128);
    float* out = (n0 < 128) ? g_p : g_cq;

    int tid = threadIdx.x;
    int tm = tid >> 4, tn = tid & 15;
    int lr = tid >> 2, lc = (tid & 3) << 2;

    unsigned long long accp[4][2];
#pragma unroll
    for (int i = 0; i < 4; i++) { accp[i][0] = 0ull; accp[i][1] = 0ull; }

    for (int k0 = 0; k0 < INW; k0 += 16) {
        float4 av = *(const float4*)&A[(size_t)(m0 + lr) * INW + k0 + lc];
        float4 bv = *(const float4*)&Wsel[(size_t)(nbase + lr) * INW + k0 + lc];
        As[lc + 0][lr] = av.x; As[lc + 1][lr] = av.y; As[lc + 2][lr] = av.z; As[lc + 3][lr] = av.w;
        Bs[lc + 0][lr] = bv.x; Bs[lc + 1][lr] = bv.y; Bs[lc + 2][lr] = bv.z; Bs[lc + 3][lr] = bv.w;
        __syncthreads();
#pragma unroll
        for (int kk = 0; kk < 16; kk++) {
            float4 a4 = *(const float4*)&As[kk][tm << 2];
            ulonglong2 b2 = *(const ulonglong2*)&Bs[kk][tn << 2];
            unsigned long long ad0 = pack2(a4.x, a4.x);
            unsigned long long ad1 = pack2(a4.y, a4.y);
            unsigned long long ad2 = pack2(a4.z, a4.z);
            unsigned long long ad3 = pack2(a4.w, a4.w);
            accp[0][0] = ffma2(ad0, b2.x, accp[0][0]);
            accp[0][1] = ffma2(ad0, b2.y, accp[0][1]);
            accp[1][0] = ffma2(ad1, b2.x, accp[1][0]);
            accp[1][1] = ffma2(ad1, b2.y, accp[1][1]);
            accp[2][0] = ffma2(ad2, b2.x, accp[2][0]);
            accp[2][1] = ffma2(ad2, b2.y, accp[2][1]);
            accp[3][0] = ffma2(ad3, b2.x, accp[3][0]);
            accp[3][1] = ffma2(ad3, b2.y, accp[3][1]);
        }
        __syncthreads();
    }
#pragma unroll
    for (int i = 0; i < 4; i++) {
        int m = m0 + (tm << 2) + i;
        int s = m >> 4, b = m & 15;
        float2 u0 = unpack2(accp[i][0]);
        float2 u1 = unpack2(accp[i][1]);
        float vals[4] = {u0.x, u0.y, u1.x, u1.y};
#pragma unroll
        for (int j = 0; j < 4; j++) {
            int nl = nbase + (tn << 2) + j;
            out[(size_t)(((b << 8) + s) << 7) + nl] = vals[j];
        }
    }
}

// ---------------- 5) pairwise scores + predictions --------------------------
// scores[b,i,j] = sum_h va[h]*tanh(p[b,i,h]+c[b,j,h]);  pred = (score >= 0)
__global__ __launch_bounds__(256) void scores_kernel(const float* __restrict__ va,
                                                     float* __restrict__ out,
                                                     int write_pred) {
    __shared__ __align__(16) float ps[32][132];
    __shared__ __align__(16) float cs[32][132];
    __shared__ float va_s[HMD];
    int b  = blockIdx.z;
    int i0 = blockIdx.y << 5, j0 = blockIdx.x << 5;
    int tid = threadIdx.x;
    if (tid < HMD) va_s[tid] = va[tid];
#pragma unroll
    for (int i = 0; i < 4; i++) {
        int f4 = tid + (i << 8);                 // 1024 float4s total
        int row = f4 >> 5;
        int col = (f4 & 31) << 2;
        *(float4*)&ps[row][col] =
            *(const float4*)&g_p[(size_t)(((b << 8) + i0 + row) << 7) + col];
        *(float4*)&cs[row][col] =
            *(const float4*)&g_cq[(size_t)(((b << 8) + j0 + row) << 7) + col];
    }
    __syncthreads();

    int tj = tid & 15, ti = tid >> 4;
    int ia = ti << 1, ja = tj << 1;
    float s00 = 0.f, s01 = 0.f, s10 = 0.f, s11 = 0.f;
#pragma unroll 4
    for (int h = 0; h < HMD; h++) {
        float v  = va_s[h];
        float pa = ps[ia][h],     pb = ps[ia + 1][h];
        float ca = cs[ja][h],     cb = cs[ja + 1][h];
        s00 += v * ftanh(pa + ca);
        s01 += v * ftanh(pa + cb);
        s10 += v * ftanh(pb + ca);
        s11 += v * ftanh(pb + cb);
    }
    int gi = i0 + ia, gj = j0 + ja;
    size_t base = ((size_t)b << 16) + ((size_t)gi << 8) + gj;
    out[base]           = s00;
    out[base + 1]       = s01;
    out[base + 256]     = s10;
    out[base + 257]     = s11;
    if (write_pred) {
        float* po = out + NSC;
        po[base]       = (s00 >= 0.f) ? 1.f : 0.f;
        po[base + 1]   = (s01 >= 0.f) ? 1.f : 0.f;
        po[base + 256] = (s10 >= 0.f) ? 1.f : 0.f;
        po[base + 257] = (s11 >= 0.f) ? 1.f : 0.f;
    }
}

// ---------------- launch -----------------------------------------------------
extern "C" void kernel_launch(void* const* d_in, const int* in_sizes, int n_in,
                              void* d_out, int out_size) {
    const int*   concepts = (const int*)d_in[0];
    // d_in[1] = concepts_lengths (all full-length; unused)
    const float* emb  = (const float*)d_in[2];
    const float* w_ih = (const float*)d_in[3];
    const float* w_hh = (const float*)d_in[4];
    const float* bias = (const float*)d_in[5];
    const float* Ua   = (const float*)d_in[6];
    const float* Wa   = (const float*)d_in[7];
    const float* va   = (const float*)d_in[8];
    float* out = (float*)d_out;

    embed_kernel<<<NROWS, 128>>>(concepts, emb);

    // layer 0
    inproj_kernel<<<dim3(32, 64), 256>>>(0, w_ih, bias);
    lstm_rec_kernel<<<128, 256>>>(0, w_hh);
    // layer 1
    inproj_kernel<<<dim3(32, 64), 256>>>(1, w_ih + 2 * G4 * EMB, bias + 2 * G4);
    lstm_rec_kernel<<<128, 256>>>(1, w_hh + 2 * G4 * HID);

    attnproj_kernel<<<dim3(4, 64), 256>>>(Ua, Wa);

    int write_pred = (out_size >= 2 * NSC) ? 1 : 0;
    scores_kernel<<<dim3(8, 8, BATCH), 256>>>(va, out, write_pred);
}

// round 5
// speedup vs baseline: 1.5887x; 1.5887x over previous
#include <cuda_runtime.h>
#include <cuda_bf16.h>

#define SQ    256
#define BATCH 16
#define EMB   512
#define HID   256
#define HMD   128
#define G4    1024            // 4*HID
#define NROWS (SQ*BATCH)      // 4096
#define INW   512             // input width both layers (E = 2H = 512)
#define NSC   (BATCH*SQ*SQ)   // 1,048,576 scores

// ---------------- scratch (device globals; no allocations allowed) ----------
__device__ float g_xa[NROWS * EMB];                 // 8 MB
__device__ float g_xb[NROWS * EMB];                 // 8 MB
__device__ float g_xproj[2 * SQ * G4 * BATCH];      // 32 MB : [dir][t][gate(1024)][b]
__device__ float g_hbuf[2][2][BATCH * HID];         // [pingpong][dir][b*256+k]
__device__ float g_p[BATCH * SQ * HMD];             // 2 MB
__device__ float g_cq[BATCH * SQ * HMD];            // 2 MB
__device__ unsigned g_arrive[2][64];                // per-dir distributed barrier flags

// ---------------- f32x2 packed math ------------------------------------------
__device__ __forceinline__ unsigned long long ffma2(unsigned long long a,
                                                    unsigned long long b,
                                                    unsigned long long c) {
    unsigned long long d;
    asm("fma.rn.f32x2 %0, %1, %2, %3;" : "=l"(d) : "l"(a), "l"(b), "l"(c));
    return d;
}
__device__ __forceinline__ unsigned long long pack2(float x, float y) {
    unsigned long long d;
    asm("mov.b64 %0, {%1, %2};" : "=l"(d) : "f"(x), "f"(y));
    return d;
}
__device__ __forceinline__ float2 unpack2(unsigned long long v) {
    float2 r;
    asm("mov.b64 {%0, %1}, %2;" : "=f"(r.x), "=f"(r.y) : "l"(v));
    return r;
}

// ---------------- scalar math helpers ----------------------------------------
__device__ __forceinline__ float ftanh(float x) {
    x = fminf(fmaxf(x, -15.f), 15.f);
    float e = __expf(2.f * x);
    return 1.f - __fdividef(2.f, e + 1.f);
}
__device__ __forceinline__ float fsig(float x) {
    x = fminf(fmaxf(x, -30.f), 30.f);
    return __fdividef(1.f, 1.f + __expf(-x));
}

// ---------------- 1) embedding gather (+ barrier flag reset) -----------------
__global__ __launch_bounds__(128) void embed_kernel(const int* __restrict__ concepts,
                                                    const float* __restrict__ emb) {
    if (blockIdx.x == 0 && threadIdx.x < 128)
        __stcg(&g_arrive[threadIdx.x >> 6][threadIdx.x & 63], 0u);
    int row = blockIdx.x;                       // s*16 + b
    int tok = concepts[row];
    const float4* src = (const float4*)(emb + (size_t)tok * EMB);
    float4* dst = (float4*)(g_xa + (size_t)row * EMB);
    dst[threadIdx.x] = src[threadIdx.x];        // 128 * float4 = 512 floats
}

// ---------------- 2) input projection GEMM: [4096,512] x [2048,512]^T -------
// out: g_xproj[((dir*256 + s)*1024 + g)*16 + b]   (b fastest for recurrence)
__global__ __launch_bounds__(256) void inproj_kernel(int layer,
                                                     const float* __restrict__ W,
                                                     const float* __restrict__ bias) {
    const float* __restrict__ A = layer ? g_xb : g_xa;
    __shared__ __align__(16) float As[16][68];
    __shared__ __align__(16) float Bs[16][68];
    int m0 = blockIdx.y << 6;
    int n0 = blockIdx.x << 6;
    int tid = threadIdx.x;
    int tm = tid >> 4, tn = tid & 15;
    int lr = tid >> 2, lc = (tid & 3) << 2;

    unsigned long long accp[4][2];
#pragma unroll
    for (int i = 0; i < 4; i++) { accp[i][0] = 0ull; accp[i][1] = 0ull; }

    for (int k0 = 0; k0 < INW; k0 += 16) {
        float4 av = *(const float4*)&A[(size_t)(m0 + lr) * INW + k0 + lc];
        float4 bv = *(const float4*)&W[(size_t)(n0 + lr) * INW + k0 + lc];
        As[lc + 0][lr] = av.x; As[lc + 1][lr] = av.y; As[lc + 2][lr] = av.z; As[lc + 3][lr] = av.w;
        Bs[lc + 0][lr] = bv.x; Bs[lc + 1][lr] = bv.y; Bs[lc + 2][lr] = bv.z; Bs[lc + 3][lr] = bv.w;
        __syncthreads();
#pragma unroll
        for (int kk = 0; kk < 16; kk++) {
            float4 a4 = *(const float4*)&As[kk][tm << 2];
            ulonglong2 b2 = *(const ulonglong2*)&Bs[kk][tn << 2];
            unsigned long long ad0 = pack2(a4.x, a4.x);
            unsigned long long ad1 = pack2(a4.y, a4.y);
            unsigned long long ad2 = pack2(a4.z, a4.z);
            unsigned long long ad3 = pack2(a4.w, a4.w);
            accp[0][0] = ffma2(ad0, b2.x, accp[0][0]);
            accp[0][1] = ffma2(ad0, b2.y, accp[0][1]);
            accp[1][0] = ffma2(ad1, b2.x, accp[1][0]);
            accp[1][1] = ffma2(ad1, b2.y, accp[1][1]);
            accp[2][0] = ffma2(ad2, b2.x, accp[2][0]);
            accp[2][1] = ffma2(ad2, b2.y, accp[2][1]);
            accp[3][0] = ffma2(ad3, b2.x, accp[3][0]);
            accp[3][1] = ffma2(ad3, b2.y, accp[3][1]);
        }
        __syncthreads();
    }
#pragma unroll
    for (int i = 0; i < 4; i++) {
        int m = m0 + (tm << 2) + i;
        int s = m >> 4, b = m & 15;
        float2 u0 = unpack2(accp[i][0]);
        float2 u1 = unpack2(accp[i][1]);
        float vals[4] = {u0.x, u0.y, u1.x, u1.y};
#pragma unroll
        for (int j = 0; j < 4; j++) {
            int n = n0 + (tn << 2) + j;
            int d = n >> 10, g = n & 1023;
            g_xproj[(size_t)((((d << 8) | s) << 10) | g) * BATCH + b] = vals[j] + bias[n];
        }
    }
}

// ---------------- 3) LSTM recurrence (persistent, 128 blocks, 256 thr) ------
// 64 CTAs/dir, each owns 4 hidden units (16 gate rows x 16 batch).
// Weights REGISTER-resident (64 floats/thread as 32 packed f32x2).
// h staged ONCE per step into padded smem (coalesced 16KB ldcg), then read
// via broadcast-friendly LDS.128. Thread = (ks 0..15, rg 0..3, bg 0..3).
#define HSTR 260                                   // h_s row stride (floats)
__global__ __launch_bounds__(256) void lstm_rec_kernel(int layer,
                                                       const float* __restrict__ whh) {
    float* __restrict__ xout = layer ? g_xa : g_xb;
    int dir = blockIdx.x >> 6;
    int gb  = blockIdx.x & 63;
    int j0  = gb << 2;                 // 4 hidden units per CTA
    int tid = threadIdx.x;
    int ks = tid >> 4;                 // k-slice 0..15 (k = ks*16 .. +15)
    int rg = (tid >> 2) & 3;           // gate index q, rows rg*4+i
    int bg = tid & 3;                  // batch group (b = bg*4+j)

    __shared__ __align__(16) float h_s[BATCH * HSTR];   // 16.6 KB
    __shared__ __align__(16) float part_s[16][16][20];  // [ks][r][b(+pad)] 20 KB
    __shared__ float gate_s[16][17];                    // [r][b]

    // ---- weights into registers, packed as k-pairs -------------------------
    unsigned long long w_ull[4][8];
#pragma unroll
    for (int i = 0; i < 4; i++) {
        const float* wr = whh + (size_t)((dir << 10) + (rg << 8) + j0 + i) * HID + (ks << 4);
#pragma unroll
        for (int m = 0; m < 4; m++) {
            float4 f = *(const float4*)&wr[m << 2];
            w_ull[i][m * 2]     = pack2(f.x, f.y);
            w_ull[i][m * 2 + 1] = pack2(f.z, f.w);
        }
    }
    if (tid < 64) {
        int b = tid & 15, u = tid >> 4;
        __stcg(&g_hbuf[0][dir][(b << 8) + j0 + u], 0.f);
    }
    float c_reg = 0.f;

    unsigned base = (unsigned)layer * 300u;
#define DIR_BARRIER(TARGET)                                                     \
    do {                                                                        \
        unsigned _tg = (TARGET);                                                \
        __syncthreads();                                                        \
        if (tid == 0) { __stcg(&g_arrive[dir][gb], _tg); }                      \
        for (;;) {                                                              \
            int ok = (tid < 64) ? (__ldcg(&g_arrive[dir][tid]) >= _tg) : 1;     \
            if (__syncthreads_count(ok) == 256) break;                          \
        }                                                                       \
        __threadfence();                                                        \
    } while (0)

    __threadfence();
    DIR_BARRIER(base + 1u);            // h(0) visible everywhere

    // readback mapping: tid -> (r = tid>>4, b = tid&15)
    int rb_r = tid >> 4, rb_b = tid & 15;
    int rb_q = rb_r >> 2, rb_u = rb_r & 3;
    int rb_off = (dir << 22) + ((rb_q << 8) + j0 + rb_u) * BATCH + rb_b;

    for (int p = 0; p < SQ; p++) {
        int t = dir ? (SQ - 1 - p) : p;
        const float* hsrc = g_hbuf[p & 1][dir];

        // ---- stage h into smem: 1024 float4, coalesced -------------------
#pragma unroll
        for (int i4 = 0; i4 < 4; i4++) {
            int idx = tid + (i4 << 8);               // float4 index 0..1023
            int b = idx >> 6;
            int k = (idx & 63) << 2;
            float4 v = __ldcg((const float4*)&hsrc[idx << 2]);
            *(float4*)&h_s[b * HSTR + k] = v;
        }
        float xp = __ldg(&g_xproj[rb_off + (t << 14)]);
        __syncthreads();

        // ---- register-tiled gates: 4 rows x 4 batches x 16 k -------------
        unsigned long long acc[4][4];
#pragma unroll
        for (int i = 0; i < 4; i++)
#pragma unroll
            for (int j = 0; j < 4; j++) acc[i][j] = 0ull;

#pragma unroll
        for (int j = 0; j < 4; j++) {
            const float* hb = &h_s[((bg << 2) + j) * HSTR + (ks << 4)];
#pragma unroll
            for (int m = 0; m < 4; m++) {
                float4 h4 = *(const float4*)&hb[m << 2];
                unsigned long long h01 = pack2(h4.x, h4.y);
                unsigned long long h23 = pack2(h4.z, h4.w);
#pragma unroll
                for (int i = 0; i < 4; i++) {
                    acc[i][j] = ffma2(w_ull[i][m * 2],     h01, acc[i][j]);
                    acc[i][j] = ffma2(w_ull[i][m * 2 + 1], h23, acc[i][j]);
                }
            }
        }

        // ---- write partials ----------------------------------------------
#pragma unroll
        for (int i = 0; i < 4; i++) {
            float2 p0 = unpack2(acc[i][0]);
            float2 p1 = unpack2(acc[i][1]);
            float2 p2 = unpack2(acc[i][2]);
            float2 p3 = unpack2(acc[i][3]);
            float4 v = make_float4(p0.x + p0.y, p1.x + p1.y, p2.x + p2.y, p3.x + p3.y);
            *(float4*)&part_s[ks][(rg << 2) + i][bg << 2] = v;
        }
        __syncthreads();

        // ---- reduce 16 k-slices; thread (r,b) owns one gate --------------
        float gsum = xp;
#pragma unroll
        for (int s2 = 0; s2 < 16; s2++) gsum += part_s[s2][rb_r][rb_b];
        gate_s[rb_r][rb_b] = gsum;
        __syncthreads();

        if (tid < 64) {
            int b = tid & 15, u = tid >> 4;
            float gi = gate_s[u][b];
            float gf = gate_s[4 + u][b];
            float gg = gate_s[8 + u][b];
            float go = gate_s[12 + u][b];
            c_reg = fsig(gf) * c_reg + fsig(gi) * ftanh(gg);
            float h = fsig(go) * ftanh(c_reg);
            __stcg(&g_hbuf[(p + 1) & 1][dir][(b << 8) + j0 + u], h);
            xout[(size_t)((t * BATCH + b) << 9) + (dir << 8) + j0 + u] = h;
            __threadfence();
        }
        DIR_BARRIER(base + 2u + (unsigned)p);
    }
#undef DIR_BARRIER
}

// ---------------- 4) attention projections ----------------------------------
// n0 in {0,64} -> Ua -> g_p[(b*256+s)*128+n] ; n0 in {128,192} -> Wa -> g_cq
__global__ __launch_bounds__(256) void attnproj_kernel(const float* __restrict__ Ua,
                                                       const float* __restrict__ Wa) {
    const float* __restrict__ A = g_xa;   // layer-1 output [s][b][512]
    __shared__ __align__(16) float As[16][68];
    __shared__ __align__(16) float Bs[16][68];
    int m0 = blockIdx.y << 6;
    int n0 = blockIdx.x << 6;
    const float* Wsel = (n0 < 128) ? Ua : Wa;
    int nbase = (n0 < 128) ? n0 : (n0 - 128);
    float* out = (n0 < 128) ? g_p : g_cq;

    int tid = threadIdx.x;
    int tm = tid >> 4, tn = tid & 15;
    int lr = tid >> 2, lc = (tid & 3) << 2;

    unsigned long long accp[4][2];
#pragma unroll
    for (int i = 0; i < 4; i++) { accp[i][0] = 0ull; accp[i][1] = 0ull; }

    for (int k0 = 0; k0 < INW; k0 += 16) {
        float4 av = *(const float4*)&A[(size_t)(m0 + lr) * INW + k0 + lc];
        float4 bv = *(const float4*)&Wsel[(size_t)(nbase + lr) * INW + k0 + lc];
        As[lc + 0][lr] = av.x; As[lc + 1][lr] = av.y; As[lc + 2][lr] = av.z; As[lc + 3][lr] = av.w;
        Bs[lc + 0][lr] = bv.x; Bs[lc + 1][lr] = bv.y; Bs[lc + 2][lr] = bv.z; Bs[lc + 3][lr] = bv.w;
        __syncthreads();
#pragma unroll
        for (int kk = 0; kk < 16; kk++) {
            float4 a4 = *(const float4*)&As[kk][tm << 2];
            ulonglong2 b2 = *(const ulonglong2*)&Bs[kk][tn << 2];
            unsigned long long ad0 = pack2(a4.x, a4.x);
            unsigned long long ad1 = pack2(a4.y, a4.y);
            unsigned long long ad2 = pack2(a4.z, a4.z);
            unsigned long long ad3 = pack2(a4.w, a4.w);
            accp[0][0] = ffma2(ad0, b2.x, accp[0][0]);
            accp[0][1] = ffma2(ad0, b2.y, accp[0][1]);
            accp[1][0] = ffma2(ad1, b2.x, accp[1][0]);
            accp[1][1] = ffma2(ad1, b2.y, accp[1][1]);
            accp[2][0] = ffma2(ad2, b2.x, accp[2][0]);
            accp[2][1] = ffma2(ad2, b2.y, accp[2][1]);
            accp[3][0] = ffma2(ad3, b2.x, accp[3][0]);
            accp[3][1] = ffma2(ad3, b2.y, accp[3][1]);
        }
        __syncthreads();
    }
#pragma unroll
    for (int i = 0; i < 4; i++) {
        int m = m0 + (tm << 2) + i;
        int s = m >> 4, b = m & 15;
        float2 u0 = unpack2(accp[i][0]);
        float2 u1 = unpack2(accp[i][1]);
        float vals[4] = {u0.x, u0.y, u1.x, u1.y};
#pragma unroll
        for (int j = 0; j < 4; j++) {
            int nl = nbase + (tn << 2) + j;
            out[(size_t)(((b << 8) + s) << 7) + nl] = vals[j];
        }
    }
}

// ---------------- 5) pairwise scores + predictions --------------------------
// scores[b,i,j] = sum_h va[h]*tanh(p[b,i,h]+c[b,j,h]);  pred = (score >= 0)
__global__ __launch_bounds__(256) void scores_kernel(const float* __restrict__ va,
                                                     float* __restrict__ out,
                                                     int write_pred) {
    __shared__ __align__(16) float ps[32][132];
    __shared__ __align__(16) float cs[32][132];
    __shared__ float va_s[HMD];
    int b  = blockIdx.z;
    int i0 = blockIdx.y << 5, j0 = blockIdx.x << 5;
    int tid = threadIdx.x;
    if (tid < HMD) va_s[tid] = va[tid];
#pragma unroll
    for (int i = 0; i < 4; i++) {
        int f4 = tid + (i << 8);                 // 1024 float4s total
        int row = f4 >> 5;
        int col = (f4 & 31) << 2;
        *(float4*)&ps[row][col] =
            *(const float4*)&g_p[(size_t)(((b << 8) + i0 + row) << 7) + col];
        *(float4*)&cs[row][col] =
            *(const float4*)&g_cq[(size_t)(((b << 8) + j0 + row) << 7) + col];
    }
    __syncthreads();

    int tj = tid & 15, ti = tid >> 4;
    int ia = ti << 1, ja = tj << 1;
    float s00 = 0.f, s01 = 0.f, s10 = 0.f, s11 = 0.f;
#pragma unroll 4
    for (int h = 0; h < HMD; h++) {
        float v  = va_s[h];
        float pa = ps[ia][h],     pb = ps[ia + 1][h];
        float ca = cs[ja][h],     cb = cs[ja + 1][h];
        s00 += v * ftanh(pa + ca);
        s01 += v * ftanh(pa + cb);
        s10 += v * ftanh(pb + ca);
        s11 += v * ftanh(pb + cb);
    }
    int gi = i0 + ia, gj = j0 + ja;
    size_t base = ((size_t)b << 16) + ((size_t)gi << 8) + gj;
    out[base]           = s00;
    out[base + 1]       = s01;
    out[base + 256]     = s10;
    out[base + 257]     = s11;
    if (write_pred) {
        float* po = out + NSC;
        po[base]       = (s00 >= 0.f) ? 1.f : 0.f;
        po[base + 1]   = (s01 >= 0.f) ? 1.f : 0.f;
        po[base + 256] = (s10 >= 0.f) ? 1.f : 0.f;
        po[base + 257] = (s11 >= 0.f) ? 1.f : 0.f;
    }
}

// ---------------- launch -----------------------------------------------------
extern "C" void kernel_launch(void* const* d_in, const int* in_sizes, int n_in,
                              void* d_out, int out_size) {
    const int*   concepts = (const int*)d_in[0];
    // d_in[1] = concepts_lengths (all full-length; unused)
    const float* emb  = (const float*)d_in[2];
    const float* w_ih = (const float*)d_in[3];
    const float* w_hh = (const float*)d_in[4];
    const float* bias = (const float*)d_in[5];
    const float* Ua   = (const float*)d_in[6];
    const float* Wa   = (const float*)d_in[7];
    const float* va   = (const float*)d_in[8];
    float* out = (float*)d_out;

    embed_kernel<<<NROWS, 128>>>(concepts, emb);

    // layer 0
    inproj_kernel<<<dim3(32, 64), 256>>>(0, w_ih, bias);
    lstm_rec_kernel<<<128, 256>>>(0, w_hh);
    // layer 1
    inproj_kernel<<<dim3(32, 64), 256>>>(1, w_ih + 2 * G4 * EMB, bias + 2 * G4);
    lstm_rec_kernel<<<128, 256>>>(1, w_hh + 2 * G4 * HID);

    attnproj_kernel<<<dim3(4, 64), 256>>>(Ua, Wa);

    int write_pred = (out_size >= 2 * NSC) ? 1 : 0;
    scores_kernel<<<dim3(8, 8, BATCH), 256>>>(va, out, write_pred);
}

// round 6
// speedup vs baseline: 1.6101x; 1.0134x over previous
#include <cuda_runtime.h>
#include <cuda_bf16.h>

#define SQ    256
#define BATCH 16
#define EMB   512
#define HID   256
#define HMD   128
#define G4    1024            // 4*HID
#define NROWS (SQ*BATCH)      // 4096
#define INW   512             // input width both layers (E = 2H = 512)
#define NSC   (BATCH*SQ*SQ)   // 1,048,576 scores

// ---------------- scratch (device globals; no allocations allowed) ----------
__device__ float g_xa[NROWS * EMB];                 // 8 MB
__device__ float g_xb[NROWS * EMB];                 // 8 MB
__device__ float g_xproj[2 * SQ * G4 * BATCH];      // 32 MB : [dir][t][gate(1024)][b]
__device__ float g_hbuf[2][2][BATCH * HID];         // [pingpong][dir][b*256+k]
__device__ float g_p[BATCH * SQ * HMD];             // 2 MB
__device__ float g_cq[BATCH * SQ * HMD];            // 2 MB
__device__ unsigned g_arrive[2][64];                // [dir][cta] publish counters

// ---------------- f32x2 packed math ------------------------------------------
__device__ __forceinline__ unsigned long long ffma2(unsigned long long a,
                                                    unsigned long long b,
                                                    unsigned long long c) {
    unsigned long long d;
    asm("fma.rn.f32x2 %0, %1, %2, %3;" : "=l"(d) : "l"(a), "l"(b), "l"(c));
    return d;
}
__device__ __forceinline__ unsigned long long pack2(float x, float y) {
    unsigned long long d;
    asm("mov.b64 %0, {%1, %2};" : "=l"(d) : "f"(x), "f"(y));
    return d;
}
__device__ __forceinline__ float2 unpack2(unsigned long long v) {
    float2 r;
    asm("mov.b64 {%0, %1}, %2;" : "=f"(r.x), "=f"(r.y) : "l"(v));
    return r;
}

// ---------------- release/acquire flag ops (no CCTL, no MEMBAR.GPU) ----------
__device__ __forceinline__ void st_release(unsigned* p, unsigned v) {
    asm volatile("st.global.release.gpu.b32 [%0], %1;" :: "l"(p), "r"(v) : "memory");
}
__device__ __forceinline__ unsigned ld_acquire(const unsigned* p) {
    unsigned v;
    asm volatile("ld.global.acquire.gpu.b32 %0, [%1];" : "=r"(v) : "l"(p) : "memory");
    return v;
}

// ---------------- scalar math helpers ----------------------------------------
__device__ __forceinline__ float ftanh(float x) {
    x = fminf(fmaxf(x, -15.f), 15.f);
    float e = __expf(2.f * x);
    return 1.f - __fdividef(2.f, e + 1.f);
}
__device__ __forceinline__ float fsig(float x) {
    x = fminf(fmaxf(x, -30.f), 30.f);
    return __fdividef(1.f, 1.f + __expf(-x));
}

// ---------------- 1) embedding gather (+ flag reset) -------------------------
__global__ __launch_bounds__(128) void embed_kernel(const int* __restrict__ concepts,
                                                    const float* __restrict__ emb) {
    if (blockIdx.x == 0 && threadIdx.x < 128)
        __stcg(&g_arrive[threadIdx.x >> 6][threadIdx.x & 63], 0u);
    int row = blockIdx.x;                       // s*16 + b
    int tok = concepts[row];
    const float4* src = (const float4*)(emb + (size_t)tok * EMB);
    float4* dst = (float4*)(g_xa + (size_t)row * EMB);
    dst[threadIdx.x] = src[threadIdx.x];        // 128 * float4 = 512 floats
}

// ---------------- 2) input projection GEMM: [4096,512] x [2048,512]^T -------
// out: g_xproj[((dir*256 + s)*1024 + g)*16 + b]   (b fastest for recurrence)
__global__ __launch_bounds__(256) void inproj_kernel(int layer,
                                                     const float* __restrict__ W,
                                                     const float* __restrict__ bias) {
    const float* __restrict__ A = layer ? g_xb : g_xa;
    __shared__ __align__(16) float As[16][68];
    __shared__ __align__(16) float Bs[16][68];
    int m0 = blockIdx.y << 6;
    int n0 = blockIdx.x << 6;
    int tid = threadIdx.x;
    int tm = tid >> 4, tn = tid & 15;
    int lr = tid >> 2, lc = (tid & 3) << 2;

    unsigned long long accp[4][2];
#pragma unroll
    for (int i = 0; i < 4; i++) { accp[i][0] = 0ull; accp[i][1] = 0ull; }

    for (int k0 = 0; k0 < INW; k0 += 16) {
        float4 av = *(const float4*)&A[(size_t)(m0 + lr) * INW + k0 + lc];
        float4 bv = *(const float4*)&W[(size_t)(n0 + lr) * INW + k0 + lc];
        As[lc + 0][lr] = av.x; As[lc + 1][lr] = av.y; As[lc + 2][lr] = av.z; As[lc + 3][lr] = av.w;
        Bs[lc + 0][lr] = bv.x; Bs[lc + 1][lr] = bv.y; Bs[lc + 2][lr] = bv.z; Bs[lc + 3][lr] = bv.w;
        __syncthreads();
#pragma unroll
        for (int kk = 0; kk < 16; kk++) {
            float4 a4 = *(const float4*)&As[kk][tm << 2];
            ulonglong2 b2 = *(const ulonglong2*)&Bs[kk][tn << 2];
            unsigned long long ad0 = pack2(a4.x, a4.x);
            unsigned long long ad1 = pack2(a4.y, a4.y);
            unsigned long long ad2 = pack2(a4.z, a4.z);
            unsigned long long ad3 = pack2(a4.w, a4.w);
            accp[0][0] = ffma2(ad0, b2.x, accp[0][0]);
            accp[0][1] = ffma2(ad0, b2.y, accp[0][1]);
            accp[1][0] = ffma2(ad1, b2.x, accp[1][0]);
            accp[1][1] = ffma2(ad1, b2.y, accp[1][1]);
            accp[2][0] = ffma2(ad2, b2.x, accp[2][0]);
            accp[2][1] = ffma2(ad2, b2.y, accp[2][1]);
            accp[3][0] = ffma2(ad3, b2.x, accp[3][0]);
            accp[3][1] = ffma2(ad3, b2.y, accp[3][1]);
        }
        __syncthreads();
    }
#pragma unroll
    for (int i = 0; i < 4; i++) {
        int m = m0 + (tm << 2) + i;
        int s = m >> 4, b = m & 15;
        float2 u0 = unpack2(accp[i][0]);
        float2 u1 = unpack2(accp[i][1]);
        float vals[4] = {u0.x, u0.y, u1.x, u1.y};
#pragma unroll
        for (int j = 0; j < 4; j++) {
            int n = n0 + (tn << 2) + j;
            int d = n >> 10, g = n & 1023;
            g_xproj[(size_t)((((d << 8) | s) << 10) | g) * BATCH + b] = vals[j] + bias[n];
        }
    }
}

// ---------------- 3) LSTM recurrence: 64 CTAs, BOTH directions per CTA ------
// CTA gb owns hidden units j0..j0+3 for fwd AND bwd. Weights for both dirs
// register-resident. Per step: fwd half then bwd half; each publish->wait gap
// is hidden behind the other direction's compute. Flags are release/acquire.
#define HSTR 260
__global__ __launch_bounds__(256) void lstm_rec_kernel(int layer,
                                                       const float* __restrict__ whh) {
    float* __restrict__ xout = layer ? g_xa : g_xb;
    int gb = blockIdx.x;               // 0..63
    int j0 = gb << 2;
    int tid = threadIdx.x;
    int ks = tid >> 4;                 // k-slice 0..15
    int rg = (tid >> 2) & 3;           // gate index q
    int bg = tid & 3;                  // batch group

    __shared__ __align__(16) float h_s[BATCH * HSTR];
    __shared__ __align__(16) float part_s[16][16][20];
    __shared__ float gate_s[16][17];

    // weights for both dirs, packed k-pairs: w_ull[dir][i][m]
    unsigned long long w_ull[2][4][8];
#pragma unroll
    for (int d = 0; d < 2; d++)
#pragma unroll
        for (int i = 0; i < 4; i++) {
            const float* wr = whh + (size_t)((d << 10) + (rg << 8) + j0 + i) * HID + (ks << 4);
#pragma unroll
            for (int m = 0; m < 4; m++) {
                float4 f = *(const float4*)&wr[m << 2];
                w_ull[d][i][m * 2]     = pack2(f.x, f.y);
                w_ull[d][i][m * 2 + 1] = pack2(f.z, f.w);
            }
        }

    // publish h(0) = 0 for both dirs
    if (tid < 128) {
        int d = tid >> 6, r = tid & 63;
        int b = r & 15, u = r >> 4;
        __stcg(&g_hbuf[0][d][(b << 8) + j0 + u], 0.f);
    }
    __syncthreads();
    unsigned base = (unsigned)(layer + 1) * 1000u;
    if (tid == 0) {
        st_release(&g_arrive[0][gb], base + 1u);
        st_release(&g_arrive[1][gb], base + 1u);
    }

    float c_f = 0.f, c_b = 0.f;
    int rb_r = tid >> 4, rb_b = tid & 15;
    int rb_q = rb_r >> 2, rb_u = rb_r & 3;
    int rb_base = ((rb_q << 8) + j0 + rb_u) * BATCH + rb_b;

// one direction-half of a timestep
#define HALF(D, T, CREG)                                                        \
    do {                                                                        \
        const int t_ = (T);                                                     \
        unsigned tg = base + 1u + (unsigned)p;                                  \
        float xp = __ldg(&g_xproj[((D) << 22) + rb_base + (t_ << 14)]);         \
        if (tid < 64)                                                           \
            while (ld_acquire(&g_arrive[D][tid]) < tg) { }                      \
        __syncthreads();                                                        \
        const float* hsrc = g_hbuf[p & 1][D];                                   \
        _Pragma("unroll")                                                       \
        for (int i4 = 0; i4 < 4; i4++) {                                        \
            int idx = tid + (i4 << 8);                                          \
            int b2_ = idx >> 6, k2_ = (idx & 63) << 2;                          \
            *(float4*)&h_s[b2_ * HSTR + k2_] =                                  \
                __ldcg((const float4*)&hsrc[idx << 2]);                         \
        }                                                                       \
        __syncthreads();                                                        \
        unsigned long long acc[4][4];                                           \
        _Pragma("unroll")                                                       \
        for (int i = 0; i < 4; i++)                                             \
            { acc[i][0]=0ull; acc[i][1]=0ull; acc[i][2]=0ull; acc[i][3]=0ull; } \
        _Pragma("unroll")                                                       \
        for (int j = 0; j < 4; j++) {                                           \
            const float* hb = &h_s[((bg << 2) + j) * HSTR + (ks << 4)];         \
            _Pragma("unroll")                                                   \
            for (int m = 0; m < 4; m++) {                                       \
                float4 h4 = *(const float4*)&hb[m << 2];                        \
                unsigned long long h01 = pack2(h4.x, h4.y);                     \
                unsigned long long h23 = pack2(h4.z, h4.w);                     \
                _Pragma("unroll")                                               \
                for (int i = 0; i < 4; i++) {                                   \
                    acc[i][j] = ffma2(w_ull[D][i][m*2],   h01, acc[i][j]);      \
                    acc[i][j] = ffma2(w_ull[D][i][m*2+1], h23, acc[i][j]);      \
                }                                                               \
            }                                                                   \
        }                                                                       \
        _Pragma("unroll")                                                       \
        for (int i = 0; i < 4; i++) {                                           \
            float2 p0 = unpack2(acc[i][0]);                                     \
            float2 p1 = unpack2(acc[i][1]);                                     \
            float2 p2 = unpack2(acc[i][2]);                                     \
            float2 p3 = unpack2(acc[i][3]);                                     \
            float4 v = make_float4(p0.x+p0.y, p1.x+p1.y, p2.x+p2.y, p3.x+p3.y); \
            *(float4*)&part_s[ks][(rg << 2) + i][bg << 2] = v;                  \
        }                                                                       \
        __syncthreads();                                                        \
        float gsum = xp;                                                        \
        _Pragma("unroll")                                                       \
        for (int s2 = 0; s2 < 16; s2++) gsum += part_s[s2][rb_r][rb_b];         \
        gate_s[rb_r][rb_b] = gsum;                                              \
        __syncthreads();                                                        \
        if (tid < 64) {                                                         \
            int b = tid & 15, u = tid >> 4;                                     \
            float gi = gate_s[u][b];                                            \
            float gf = gate_s[4 + u][b];                                        \
            float gg = gate_s[8 + u][b];                                        \
            float go = gate_s[12 + u][b];                                       \
            CREG = fsig(gf) * CREG + fsig(gi) * ftanh(gg);                      \
            float h = fsig(go) * ftanh(CREG);                                   \
            __stcg(&g_hbuf[(p + 1) & 1][D][(b << 8) + j0 + u], h);              \
            xout[(size_t)((t_ * BATCH + b) << 9) + ((D) << 8) + j0 + u] = h;    \
        }                                                                       \
        __syncthreads();                                                        \
        if (tid == 0) st_release(&g_arrive[D][gb], tg + 1u);                    \
    } while (0)

    for (int p = 0; p < SQ; p++) {
        HALF(0, p, c_f);
        HALF(1, SQ - 1 - p, c_b);
    }
#undef HALF
}

// ---------------- 4) attention projections ----------------------------------
// n0 in {0,64} -> Ua -> g_p[(b*256+s)*128+n] ; n0 in {128,192} -> Wa -> g_cq
__global__ __launch_bounds__(256) void attnproj_kernel(const float* __restrict__ Ua,
                                                       const float* __restrict__ Wa) {
    const float* __restrict__ A = g_xa;   // layer-1 output [s][b][512]
    __shared__ __align__(16) float As[16][68];
    __shared__ __align__(16) float Bs[16][68];
    int m0 = blockIdx.y << 6;
    int n0 = blockIdx.x << 6;
    const float* Wsel = (n0 < 128) ? Ua : Wa;
    int nbase = (n0 < 128) ? n0 : (n0 - 128);
    float* out = (n0 < 128) ? g_p : g_cq;

    int tid = threadIdx.x;
    int tm = tid >> 4, tn = tid & 15;
    int lr = tid >> 2, lc = (tid & 3) << 2;

    unsigned long long accp[4][2];
#pragma unroll
    for (int i = 0; i < 4; i++) { accp[i][0] = 0ull; accp[i][1] = 0ull; }

    for (int k0 = 0; k0 < INW; k0 += 16) {
        float4 av = *(const float4*)&A[(size_t)(m0 + lr) * INW + k0 + lc];
        float4 bv = *(const float4*)&Wsel[(size_t)(nbase + lr) * INW + k0 + lc];
        As[lc + 0][lr] = av.x; As[lc + 1][lr] = av.y; As[lc + 2][lr] = av.z; As[lc + 3][lr] = av.w;
        Bs[lc + 0][lr] = bv.x; Bs[lc + 1][lr] = bv.y; Bs[lc + 2][lr] = bv.z; Bs[lc + 3][lr] = bv.w;
        __syncthreads();
#pragma unroll
        for (int kk = 0; kk < 16; kk++) {
            float4 a4 = *(const float4*)&As[kk][tm << 2];
            ulonglong2 b2 = *(const ulonglong2*)&Bs[kk][tn << 2];
            unsigned long long ad0 = pack2(a4.x, a4.x);
            unsigned long long ad1 = pack2(a4.y, a4.y);
            unsigned long long ad2 = pack2(a4.z, a4.z);
            unsigned long long ad3 = pack2(a4.w, a4.w);
            accp[0][0] = ffma2(ad0, b2.x, accp[0][0]);
            accp[0][1] = ffma2(ad0, b2.y, accp[0][1]);
            accp[1][0] = ffma2(ad1, b2.x, accp[1][0]);
            accp[1][1] = ffma2(ad1, b2.y, accp[1][1]);
            accp[2][0] = ffma2(ad2, b2.x, accp[2][0]);
            accp[2][1] = ffma2(ad2, b2.y, accp[2][1]);
            accp[3][0] = ffma2(ad3, b2.x, accp[3][0]);
            accp[3][1] = ffma2(ad3, b2.y, accp[3][1]);
        }
        __syncthreads();
    }
#pragma unroll
    for (int i = 0; i < 4; i++) {
        int m = m0 + (tm << 2) + i;
        int s = m >> 4, b = m & 15;
        float2 u0 = unpack2(accp[i][0]);
        float2 u1 = unpack2(accp[i][1]);
        float vals[4] = {u0.x, u0.y, u1.x, u1.y};
#pragma unroll
        for (int j = 0; j < 4; j++) {
            int nl = nbase + (tn << 2) + j;
            out[(size_t)(((b << 8) + s) << 7) + nl] = vals[j];
        }
    }
}

// ---------------- 5) pairwise scores + predictions --------------------------
// scores[b,i,j] = sum_h va[h]*tanh(p[b,i,h]+c[b,j,h]);  pred = (score >= 0)
__global__ __launch_bounds__(256) void scores_kernel(const float* __restrict__ va,
                                                     float* __restrict__ out,
                                                     int write_pred) {
    __shared__ __align__(16) float ps[32][132];
    __shared__ __align__(16) float cs[32][132];
    __shared__ float va_s[HMD];
    int b  = blockIdx.z;
    int i0 = blockIdx.y << 5, j0 = blockIdx.x << 5;
    int tid = threadIdx.x;
    if (tid < HMD) va_s[tid] = va[tid];
#pragma unroll
    for (int i = 0; i < 4; i++) {
        int f4 = tid + (i << 8);                 // 1024 float4s total
        int row = f4 >> 5;
        int col = (f4 & 31) << 2;
        *(float4*)&ps[row][col] =
            *(const float4*)&g_p[(size_t)(((b << 8) + i0 + row) << 7) + col];
        *(float4*)&cs[row][col] =
            *(const float4*)&g_cq[(size_t)(((b << 8) + j0 + row) << 7) + col];
    }
    __syncthreads();

    int tj = tid & 15, ti = tid >> 4;
    int ia = ti << 1, ja = tj << 1;
    float s00 = 0.f, s01 = 0.f, s10 = 0.f, s11 = 0.f;
#pragma unroll 4
    for (int h = 0; h < HMD; h++) {
        float v  = va_s[h];
        float pa = ps[ia][h],     pb = ps[ia + 1][h];
        float ca = cs[ja][h],     cb = cs[ja + 1][h];
        s00 += v * ftanh(pa + ca);
        s01 += v * ftanh(pa + cb);
        s10 += v * ftanh(pb + ca);
        s11 += v * ftanh(pb + cb);
    }
    int gi = i0 + ia, gj = j0 + ja;
    size_t base = ((size_t)b << 16) + ((size_t)gi << 8) + gj;
    out[base]           = s00;
    out[base + 1]       = s01;
    out[base + 256]     = s10;
    out[base + 257]     = s11;
    if (write_pred) {
        float* po = out + NSC;
        po[base]       = (s00 >= 0.f) ? 1.f : 0.f;
        po[base + 1]   = (s01 >= 0.f) ? 1.f : 0.f;
        po[base + 256] = (s10 >= 0.f) ? 1.f : 0.f;
        po[base + 257] = (s11 >= 0.f) ? 1.f : 0.f;
    }
}

// ---------------- launch -----------------------------------------------------
extern "C" void kernel_launch(void* const* d_in, const int* in_sizes, int n_in,
                              void* d_out, int out_size) {
    const int*   concepts = (const int*)d_in[0];
    // d_in[1] = concepts_lengths (all full-length; unused)
    const float* emb  = (const float*)d_in[2];
    const float* w_ih = (const float*)d_in[3];
    const float* w_hh = (const float*)d_in[4];
    const float* bias = (const float*)d_in[5];
    const float* Ua   = (const float*)d_in[6];
    const float* Wa   = (const float*)d_in[7];
    const float* va   = (const float*)d_in[8];
    float* out = (float*)d_out;

    embed_kernel<<<NROWS, 128>>>(concepts, emb);

    // layer 0
    inproj_kernel<<<dim3(32, 64), 256>>>(0, w_ih, bias);
    lstm_rec_kernel<<<64, 256>>>(0, w_hh);
    // layer 1
    inproj_kernel<<<dim3(32, 64), 256>>>(1, w_ih + 2 * G4 * EMB, bias + 2 * G4);
    lstm_rec_kernel<<<64, 256>>>(1, w_hh + 2 * G4 * HID);

    attnproj_kernel<<<dim3(4, 64), 256>>>(Ua, Wa);

    int write_pred = (out_size >= 2 * NSC) ? 1 : 0;
    scores_kernel<<<dim3(8, 8, BATCH), 256>>>(va, out, write_pred);
}

// round 7
// speedup vs baseline: 2.1155x; 1.3139x over previous
#include <cuda_runtime.h>
#include <cuda_bf16.h>

#define SQ    256
#define BATCH 16
#define EMB   512
#define HID   256
#define HMD   128
#define G4    1024            // 4*HID
#define NROWS (SQ*BATCH)      // 4096
#define INW   512             // input width both layers (E = 2H = 512)
#define NSC   (BATCH*SQ*SQ)   // 1,048,576 scores

// ---------------- scratch (device globals; no allocations allowed) ----------
__device__ float g_xa[NROWS * EMB];                 // 8 MB
__device__ float g_xb[NROWS * EMB];                 // 8 MB
__device__ float g_xproj[2 * SQ * G4 * BATCH];      // 32 MB : [dir][t][gate(1024)][b]
__device__ float g_hbuf[2][2][BATCH * HID];         // [pingpong][dir][b*256+k]
__device__ float g_p[BATCH * SQ * HMD];             // 2 MB
__device__ float g_cq[BATCH * SQ * HMD];            // 2 MB
__device__ unsigned g_arrive[2][4][16];             // [dir][bgroup][ug] publish tags

// ---------------- f32x2 packed math ------------------------------------------
__device__ __forceinline__ unsigned long long ffma2(unsigned long long a,
                                                    unsigned long long b,
                                                    unsigned long long c) {
    unsigned long long d;
    asm("fma.rn.f32x2 %0, %1, %2, %3;" : "=l"(d) : "l"(a), "l"(b), "l"(c));
    return d;
}
__device__ __forceinline__ unsigned long long pack2(float x, float y) {
    unsigned long long d;
    asm("mov.b64 %0, {%1, %2};" : "=l"(d) : "f"(x), "f"(y));
    return d;
}
__device__ __forceinline__ float2 unpack2(unsigned long long v) {
    float2 r;
    asm("mov.b64 {%0, %1}, %2;" : "=f"(r.x), "=f"(r.y) : "l"(v));
    return r;
}

// ---------------- release/acquire flag ops ------------------------------------
__device__ __forceinline__ void st_release(unsigned* p, unsigned v) {
    asm volatile("st.global.release.gpu.b32 [%0], %1;" :: "l"(p), "r"(v) : "memory");
}
__device__ __forceinline__ unsigned ld_acquire(const unsigned* p) {
    unsigned v;
    asm volatile("ld.global.acquire.gpu.b32 %0, [%1];" : "=r"(v) : "l"(p) : "memory");
    return v;
}

// ---------------- scalar math helpers ----------------------------------------
__device__ __forceinline__ float ftanh(float x) {
    x = fminf(fmaxf(x, -15.f), 15.f);
    float e = __expf(2.f * x);
    return 1.f - __fdividef(2.f, e + 1.f);
}
__device__ __forceinline__ float fsig(float x) {
    x = fminf(fmaxf(x, -30.f), 30.f);
    return __fdividef(1.f, 1.f + __expf(-x));
}

// ---------------- 1) embedding gather (+ flag reset) -------------------------
__global__ __launch_bounds__(128) void embed_kernel(const int* __restrict__ concepts,
                                                    const float* __restrict__ emb) {
    if (blockIdx.x == 0)
        __stcg(&((unsigned*)g_arrive)[threadIdx.x], 0u);   // 128 flags
    int row = blockIdx.x;                       // s*16 + b
    int tok = concepts[row];
    const float4* src = (const float4*)(emb + (size_t)tok * EMB);
    float4* dst = (float4*)(g_xa + (size_t)row * EMB);
    dst[threadIdx.x] = src[threadIdx.x];        // 128 * float4 = 512 floats
}

// ---------------- 2) input projection GEMM: [4096,512] x [2048,512]^T -------
// 128x128 block tile, 8x8 micro-tile, FFMA2.  out: g_xproj[((d*256+s)*1024+g)*16+b]
__global__ __launch_bounds__(256, 2) void inproj_kernel(int layer,
                                                        const float* __restrict__ W,
                                                        const float* __restrict__ bias) {
    const float* __restrict__ A = layer ? g_xb : g_xa;
    __shared__ __align__(16) float As[16][132];
    __shared__ __align__(16) float Bs[16][132];
    int m0 = blockIdx.y << 7;
    int n0 = blockIdx.x << 7;
    int tid = threadIdx.x;
    int tm = tid >> 4, tn = tid & 15;          // 16x16 threads, 8x8 each
    int lr = tid >> 1, lc = (tid & 1) << 3;    // loader: row 0..127, col 0/8

    unsigned long long accp[8][4];
#pragma unroll
    for (int i = 0; i < 8; i++)
#pragma unroll
        for (int j = 0; j < 4; j++) accp[i][j] = 0ull;

    for (int k0 = 0; k0 < INW; k0 += 16) {
        float4 a0 = *(const float4*)&A[(size_t)(m0 + lr) * INW + k0 + lc];
        float4 a1 = *(const float4*)&A[(size_t)(m0 + lr) * INW + k0 + lc + 4];
        float4 b0 = *(const float4*)&W[(size_t)(n0 + lr) * INW + k0 + lc];
        float4 b1 = *(const float4*)&W[(size_t)(n0 + lr) * INW + k0 + lc + 4];
        As[lc + 0][lr] = a0.x; As[lc + 1][lr] = a0.y; As[lc + 2][lr] = a0.z; As[lc + 3][lr] = a0.w;
        As[lc + 4][lr] = a1.x; As[lc + 5][lr] = a1.y; As[lc + 6][lr] = a1.z; As[lc + 7][lr] = a1.w;
        Bs[lc + 0][lr] = b0.x; Bs[lc + 1][lr] = b0.y; Bs[lc + 2][lr] = b0.z; Bs[lc + 3][lr] = b0.w;
        Bs[lc + 4][lr] = b1.x; Bs[lc + 5][lr] = b1.y; Bs[lc + 6][lr] = b1.z; Bs[lc + 7][lr] = b1.w;
        __syncthreads();
#pragma unroll
        for (int kk = 0; kk < 16; kk++) {
            float4 x0 = *(const float4*)&As[kk][tm << 3];
            float4 x1 = *(const float4*)&As[kk][(tm << 3) + 4];
            float4 y0 = *(const float4*)&Bs[kk][tn << 3];
            float4 y1 = *(const float4*)&Bs[kk][(tn << 3) + 4];
            unsigned long long bb[4] = {pack2(y0.x, y0.y), pack2(y0.z, y0.w),
                                        pack2(y1.x, y1.y), pack2(y1.z, y1.w)};
            float av[8] = {x0.x, x0.y, x0.z, x0.w, x1.x, x1.y, x1.z, x1.w};
#pragma unroll
            for (int i = 0; i < 8; i++) {
                unsigned long long ad = pack2(av[i], av[i]);
#pragma unroll
                for (int j = 0; j < 4; j++) accp[i][j] = ffma2(ad, bb[j], accp[i][j]);
            }
        }
        __syncthreads();
    }
#pragma unroll
    for (int i = 0; i < 8; i++) {
        int m = m0 + (tm << 3) + i;
        int s = m >> 4, b = m & 15;
#pragma unroll
        for (int j = 0; j < 4; j++) {
            float2 u = unpack2(accp[i][j]);
            int n = n0 + (tn << 3) + (j << 1);
            int d0 = n >> 10, g0 = n & 1023;
            g_xproj[(size_t)((((d0 << 8) | s) << 10) | g0) * BATCH + b] = u.x + bias[n];
            int n1 = n + 1;
            int d1 = n1 >> 10, g1 = n1 & 1023;
            g_xproj[(size_t)((((d1 << 8) | s) << 10) | g1) * BATCH + b] = u.y + bias[n1];
        }
    }
}

// ---------------- 3) LSTM recurrence: BATCH-SPLIT, 128 CTAs ------------------
// CTA = (dir, bgroup 0..3, ug 0..15): 16 units x 4 gates x 4 batches.
// Sync domain = 16 CTAs (same dir+bgroup). h staged = 4KB/step.
// Thread (compute) = (ks 0..15, u 0..15): 4 gates x 4 batches x 16k.
__global__ __launch_bounds__(256) void lstm_rec_kernel(int layer,
                                                       const float* __restrict__ whh) {
    float* __restrict__ xout = layer ? g_xa : g_xb;
    int cta = blockIdx.x;
    int dir = cta >> 6;
    int gbp = (cta >> 4) & 3;          // batch group: batches gbp*4..+3
    int ug  = cta & 15;                // unit group: units ug*16..+15
    int j0  = ug << 4;
    int b0g = gbp << 2;
    int tid = threadIdx.x;
    int ks = tid >> 4;                 // k-slice (k = ks*16..+15)
    int uu = tid & 15;                 // unit within group

    __shared__ __align__(16) float h_s[4 * 260];           // [b][k] 4KB
    __shared__ __align__(16) float part_s[16][4][16][4];   // [ks][q][u][b] 16KB
    __shared__ float gate_s[4][16][4];                     // [q][u][b]

    // weights: rows q*256 + j0 + uu, q = 0..3; k-slice ks*16..+15
    unsigned long long w_ull[4][8];
#pragma unroll
    for (int q = 0; q < 4; q++) {
        const float* wr = whh + (size_t)((dir << 10) + (q << 8) + j0 + uu) * HID + (ks << 4);
#pragma unroll
        for (int m = 0; m < 4; m++) {
            float4 f = *(const float4*)&wr[m << 2];
            w_ull[q][m * 2]     = pack2(f.x, f.y);
            w_ull[q][m * 2 + 1] = pack2(f.z, f.w);
        }
    }
    // publish h(0) = 0 for our (b,u) set
    if (tid < 64) {
        int b = tid & 3, u = tid >> 2;
        __stcg(&g_hbuf[0][dir][((b0g + b) << 8) + j0 + u], 0.f);
    }
    __syncthreads();
    unsigned base = (unsigned)(layer + 1) * 1000u;
    unsigned* flags = &g_arrive[dir][gbp][0];
    if (tid == 0) st_release(&flags[ug], base);

    float c_reg = 0.f;                 // thread tid<64 owns (u = tid>>2, b = tid&3)

    // reduce mapping: thread = (q = tid>>6, u = (tid>>2)&15, b = tid&3)
    int rd_q = tid >> 6, rd_u = (tid >> 2) & 15, rd_b = tid & 3;
    int xp_base = ((rd_q << 8) + j0 + rd_u) * BATCH + b0g + rd_b;

    for (int p = 0; p < SQ; p++) {
        int t = dir ? (SQ - 1 - p) : p;
        unsigned tg = base + (unsigned)p;
        float xp = __ldg(&g_xproj[(dir << 22) + xp_base + (t << 14)]);
        if (tid < 16)
            while (ld_acquire(&flags[tid]) < tg) { }
        __syncthreads();

        // stage h: 4 batches x 256 k = 256 float4, one per thread
        {
            int b = tid >> 6, k4 = tid & 63;
            *(float4*)&h_s[b * 260 + (k4 << 2)] =
                __ldcg((const float4*)&g_hbuf[p & 1][dir][((b0g + b) << 8) + (k4 << 2)]);
        }
        __syncthreads();

        // compute: 4 gates x 4 batches x 16 k per thread
        unsigned long long acc[4][4];
#pragma unroll
        for (int q = 0; q < 4; q++)
#pragma unroll
            for (int b = 0; b < 4; b++) acc[q][b] = 0ull;
#pragma unroll
        for (int b = 0; b < 4; b++) {
            const float* hb = &h_s[b * 260 + (ks << 4)];
#pragma unroll
            for (int m = 0; m < 4; m++) {
                float4 h4 = *(const float4*)&hb[m << 2];
                unsigned long long h01 = pack2(h4.x, h4.y);
                unsigned long long h23 = pack2(h4.z, h4.w);
#pragma unroll
                for (int q = 0; q < 4; q++) {
                    acc[q][b] = ffma2(w_ull[q][m * 2],     h01, acc[q][b]);
                    acc[q][b] = ffma2(w_ull[q][m * 2 + 1], h23, acc[q][b]);
                }
            }
        }
#pragma unroll
        for (int q = 0; q < 4; q++) {
            float2 p0 = unpack2(acc[q][0]);
            float2 p1 = unpack2(acc[q][1]);
            float2 p2 = unpack2(acc[q][2]);
            float2 p3 = unpack2(acc[q][3]);
            *(float4*)&part_s[ks][q][uu][0] =
                make_float4(p0.x + p0.y, p1.x + p1.y, p2.x + p2.y, p3.x + p3.y);
        }
        __syncthreads();

        // reduce 16 k-slices
        float gsum = xp;
#pragma unroll
        for (int s2 = 0; s2 < 16; s2++) gsum += part_s[s2][rd_q][rd_u][rd_b];
        gate_s[rd_q][rd_u][rd_b] = gsum;
        __syncthreads();

        // activations + publish (64 threads: u = tid>>2, b = tid&3)
        if (tid < 64) {
            int b = tid & 3, u = tid >> 2;
            float gi = gate_s[0][u][b];
            float gf = gate_s[1][u][b];
            float gg = gate_s[2][u][b];
            float go = gate_s[3][u][b];
            c_reg = fsig(gf) * c_reg + fsig(gi) * ftanh(gg);
            float h = fsig(go) * ftanh(c_reg);
            __stcg(&g_hbuf[(p + 1) & 1][dir][((b0g + b) << 8) + j0 + u], h);
            xout[(size_t)((t * BATCH + b0g + b) << 9) + (dir << 8) + j0 + u] = h;
        }
        __syncthreads();
        if (tid == 0) st_release(&flags[ug], tg + 1u);
    }
}

// ---------------- 4) attention projections ----------------------------------
// n0 in {0,64} -> Ua -> g_p[(b*256+s)*128+n] ; n0 in {128,192} -> Wa -> g_cq
__global__ __launch_bounds__(256) void attnproj_kernel(const float* __restrict__ Ua,
                                                       const float* __restrict__ Wa) {
    const float* __restrict__ A = g_xa;   // layer-1 output [s][b][512]
    __shared__ __align__(16) float As[16][68];
    __shared__ __align__(16) float Bs[16][68];
    int m0 = blockIdx.y << 6;
    int n0 = blockIdx.x << 6;
    const float* Wsel = (n0 < 128) ? Ua : Wa;
    int nbase = (n0 < 128) ? n0 : (n0 - 128);
    float* out = (n0 < 128) ? g_p : g_cq;

    int tid = threadIdx.x;
    int tm = tid >> 4, tn = tid & 15;
    int lr = tid >> 2, lc = (tid & 3) << 2;

    unsigned long long accp[4][2];
#pragma unroll
    for (int i = 0; i < 4; i++) { accp[i][0] = 0ull; accp[i][1] = 0ull; }

    for (int k0 = 0; k0 < INW; k0 += 16) {
        float4 av = *(const float4*)&A[(size_t)(m0 + lr) * INW + k0 + lc];
        float4 bv = *(const float4*)&Wsel[(size_t)(nbase + lr) * INW + k0 + lc];
        As[lc + 0][lr] = av.x; As[lc + 1][lr] = av.y; As[lc + 2][lr] = av.z; As[lc + 3][lr] = av.w;
        Bs[lc + 0][lr] = bv.x; Bs[lc + 1][lr] = bv.y; Bs[lc + 2][lr] = bv.z; Bs[lc + 3][lr] = bv.w;
        __syncthreads();
#pragma unroll
        for (int kk = 0; kk < 16; kk++) {
            float4 a4 = *(const float4*)&As[kk][tm << 2];
            ulonglong2 b2 = *(const ulonglong2*)&Bs[kk][tn << 2];
            unsigned long long ad0 = pack2(a4.x, a4.x);
            unsigned long long ad1 = pack2(a4.y, a4.y);
            unsigned long long ad2 = pack2(a4.z, a4.z);
            unsigned long long ad3 = pack2(a4.w, a4.w);
            accp[0][0] = ffma2(ad0, b2.x, accp[0][0]);
            accp[0][1] = ffma2(ad0, b2.y, accp[0][1]);
            accp[1][0] = ffma2(ad1, b2.x, accp[1][0]);
            accp[1][1] = ffma2(ad1, b2.y, accp[1][1]);
            accp[2][0] = ffma2(ad2, b2.x, accp[2][0]);
            accp[2][1] = ffma2(ad2, b2.y, accp[2][1]);
            accp[3][0] = ffma2(ad3, b2.x, accp[3][0]);
            accp[3][1] = ffma2(ad3, b2.y, accp[3][1]);
        }
        __syncthreads();
    }
#pragma unroll
    for (int i = 0; i < 4; i++) {
        int m = m0 + (tm << 2) + i;
        int s = m >> 4, b = m & 15;
        float2 u0 = unpack2(accp[i][0]);
        float2 u1 = unpack2(accp[i][1]);
        float vals[4] = {u0.x, u0.y, u1.x, u1.y};
#pragma unroll
        for (int j = 0; j < 4; j++) {
            int nl = nbase + (tn << 2) + j;
            out[(size_t)(((b << 8) + s) << 7) + nl] = vals[j];
        }
    }
}

// ---------------- 5) pairwise scores + predictions --------------------------
// scores[b,i,j] = sum_h va[h]*tanh(p[b,i,h]+c[b,j,h]);  pred = (score >= 0)
__global__ __launch_bounds__(256) void scores_kernel(const float* __restrict__ va,
                                                     float* __restrict__ out,
                                                     int write_pred) {
    __shared__ __align__(16) float ps[32][132];
    __shared__ __align__(16) float cs[32][132];
    __shared__ float va_s[HMD];
    int b  = blockIdx.z;
    int i0 = blockIdx.y << 5, j0 = blockIdx.x << 5;
    int tid = threadIdx.x;
    if (tid < HMD) va_s[tid] = va[tid];
#pragma unroll
    for (int i = 0; i < 4; i++) {
        int f4 = tid + (i << 8);                 // 1024 float4s total
        int row = f4 >> 5;
        int col = (f4 & 31) << 2;
        *(float4*)&ps[row][col] =
            *(const float4*)&g_p[(size_t)(((b << 8) + i0 + row) << 7) + col];
        *(float4*)&cs[row][col] =
            *(const float4*)&g_cq[(size_t)(((b << 8) + j0 + row) << 7) + col];
    }
    __syncthreads();

    int tj = tid & 15, ti = tid >> 4;
    int ia = ti << 1, ja = tj << 1;
    float s00 = 0.f, s01 = 0.f, s10 = 0.f, s11 = 0.f;
#pragma unroll 4
    for (int h = 0; h < HMD; h++) {
        float v  = va_s[h];
        float pa = ps[ia][h],     pb = ps[ia + 1][h];
        float ca = cs[ja][h],     cb = cs[ja + 1][h];
        s00 += v * ftanh(pa + ca);
        s01 += v * ftanh(pa + cb);
        s10 += v * ftanh(pb + ca);
        s11 += v * ftanh(pb + cb);
    }
    int gi = i0 + ia, gj = j0 + ja;
    size_t base = ((size_t)b << 16) + ((size_t)gi << 8) + gj;
    out[base]           = s00;
    out[base + 1]       = s01;
    out[base + 256]     = s10;
    out[base + 257]     = s11;
    if (write_pred) {
        float* po = out + NSC;
        po[base]       = (s00 >= 0.f) ? 1.f : 0.f;
        po[base + 1]   = (s01 >= 0.f) ? 1.f : 0.f;
        po[base + 256] = (s10 >= 0.f) ? 1.f : 0.f;
        po[base + 257] = (s11 >= 0.f) ? 1.f : 0.f;
    }
}

// ---------------- launch -----------------------------------------------------
extern "C" void kernel_launch(void* const* d_in, const int* in_sizes, int n_in,
                              void* d_out, int out_size) {
    const int*   concepts = (const int*)d_in[0];
    // d_in[1] = concepts_lengths (all full-length; unused)
    const float* emb  = (const float*)d_in[2];
    const float* w_ih = (const float*)d_in[3];
    const float* w_hh = (const float*)d_in[4];
    const float* bias = (const float*)d_in[5];
    const float* Ua   = (const float*)d_in[6];
    const float* Wa   = (const float*)d_in[7];
    const float* va   = (const float*)d_in[8];
    float* out = (float*)d_out;

    embed_kernel<<<NROWS, 128>>>(concepts, emb);

    // layer 0
    inproj_kernel<<<dim3(16, 32), 256>>>(0, w_ih, bias);
    lstm_rec_kernel<<<128, 256>>>(0, w_hh);
    // layer 1
    inproj_kernel<<<dim3(16, 32), 256>>>(1, w_ih + 2 * G4 * EMB, bias + 2 * G4);
    lstm_rec_kernel<<<128, 256>>>(1, w_hh + 2 * G4 * HID);

    attnproj_kernel<<<dim3(4, 64), 256>>>(Ua, Wa);

    int write_pred = (out_size >= 2 * NSC) ? 1 : 0;
    scores_kernel<<<dim3(8, 8, BATCH), 256>>>(va, out, write_pred);
}

// round 8
// speedup vs baseline: 2.3141x; 1.0938x over previous
#include <cuda_runtime.h>
#include <cuda_bf16.h>

#define SQ    256
#define BATCH 16
#define EMB   512
#define HID   256
#define HMD   128
#define G4    1024            // 4*HID
#define NROWS (SQ*BATCH)      // 4096
#define INW   512             // input width both layers (E = 2H = 512)
#define NSC   (BATCH*SQ*SQ)   // 1,048,576 scores

// ---------------- scratch (device globals; no allocations allowed) ----------
__device__ float g_xa[NROWS * EMB];                 // 8 MB
__device__ float g_xb[NROWS * EMB];                 // 8 MB
__device__ float g_xproj[2 * SQ * G4 * BATCH];      // 32 MB : [dir][t][gate(1024)][b]
__device__ float g_p[BATCH * SQ * HMD];             // 2 MB
__device__ float g_cq[BATCH * SQ * HMD];            // 2 MB

// ---------------- f32x2 packed math ------------------------------------------
__device__ __forceinline__ unsigned long long ffma2(unsigned long long a,
                                                    unsigned long long b,
                                                    unsigned long long c) {
    unsigned long long d;
    asm("fma.rn.f32x2 %0, %1, %2, %3;" : "=l"(d) : "l"(a), "l"(b), "l"(c));
    return d;
}
__device__ __forceinline__ unsigned long long pack2(float x, float y) {
    unsigned long long d;
    asm("mov.b64 %0, {%1, %2};" : "=l"(d) : "f"(x), "f"(y));
    return d;
}
__device__ __forceinline__ float2 unpack2(unsigned long long v) {
    float2 r;
    asm("mov.b64 {%0, %1}, %2;" : "=f"(r.x), "=f"(r.y) : "l"(v));
    return r;
}

// ---------------- cluster / mbarrier helpers ---------------------------------
__device__ __forceinline__ unsigned smem_u32(const void* p) {
    unsigned a;
    asm("{ .reg .u64 t; cvta.to.shared.u64 t, %1; cvt.u32.u64 %0, t; }"
        : "=r"(a) : "l"(p));
    return a;
}
__device__ __forceinline__ unsigned mapa_u32(unsigned addr, unsigned rank) {
    unsigned r;
    asm("mapa.shared::cluster.u32 %0, %1, %2;" : "=r"(r) : "r"(addr), "r"(rank));
    return r;
}
__device__ __forceinline__ void st_cluster_v4(unsigned addr, float4 v) {
    asm volatile("st.shared::cluster.v4.f32 [%0], {%1, %2, %3, %4};"
                 :: "r"(addr), "f"(v.x), "f"(v.y), "f"(v.z), "f"(v.w) : "memory");
}
__device__ __forceinline__ void mbar_init(unsigned addr, unsigned cnt) {
    asm volatile("mbarrier.init.shared.b64 [%0], %1;" :: "r"(addr), "r"(cnt) : "memory");
}
__device__ __forceinline__ void mbar_arrive_rank(unsigned local_mbar, unsigned rank) {
    asm volatile(
        "{ .reg .b32 ra; mapa.shared::cluster.u32 ra, %0, %1;\n\t"
        "mbarrier.arrive.release.cluster.shared::cluster.b64 _, [ra]; }"
        :: "r"(local_mbar), "r"(rank) : "memory");
}
__device__ __forceinline__ void mbar_wait(unsigned mbar, unsigned parity) {
    unsigned done = 0;
    while (!done) {
        asm volatile(
            "{ .reg .pred p;\n\t"
            "mbarrier.try_wait.parity.acquire.cluster.shared::cta.b64 p, [%1], %2, 0x989680;\n\t"
            "selp.b32 %0, 1, 0, p; }"
            : "=r"(done) : "r"(mbar), "r"(parity) : "memory");
    }
}

// ---------------- scalar math helpers ----------------------------------------
__device__ __forceinline__ float ftanh(float x) {
    x = fminf(fmaxf(x, -15.f), 15.f);
    float e = __expf(2.f * x);
    return 1.f - __fdividef(2.f, e + 1.f);
}
__device__ __forceinline__ float fsig(float x) {
    x = fminf(fmaxf(x, -30.f), 30.f);
    return __fdividef(1.f, 1.f + __expf(-x));
}

// ---------------- 1) embedding gather ----------------------------------------
__global__ __launch_bounds__(128) void embed_kernel(const int* __restrict__ concepts,
                                                    const float* __restrict__ emb) {
    int row = blockIdx.x;                       // s*16 + b
    int tok = concepts[row];
    const float4* src = (const float4*)(emb + (size_t)tok * EMB);
    float4* dst = (float4*)(g_xa + (size_t)row * EMB);
    dst[threadIdx.x] = src[threadIdx.x];        // 128 * float4 = 512 floats
}

// ---------------- 2) input projection GEMM: [4096,512] x [2048,512]^T -------
// 128x128 block tile, 8x8 micro-tile, FFMA2.  out: g_xproj[((d*256+s)*1024+g)*16+b]
__global__ __launch_bounds__(256, 2) void inproj_kernel(int layer,
                                                        const float* __restrict__ W,
                                                        const float* __restrict__ bias) {
    const float* __restrict__ A = layer ? g_xb : g_xa;
    __shared__ __align__(16) float As[16][132];
    __shared__ __align__(16) float Bs[16][132];
    int m0 = blockIdx.y << 7;
    int n0 = blockIdx.x << 7;
    int tid = threadIdx.x;
    int tm = tid >> 4, tn = tid & 15;          // 16x16 threads, 8x8 each
    int lr = tid >> 1, lc = (tid & 1) << 3;    // loader: row 0..127, col 0/8

    unsigned long long accp[8][4];
#pragma unroll
    for (int i = 0; i < 8; i++)
#pragma unroll
        for (int j = 0; j < 4; j++) accp[i][j] = 0ull;

    for (int k0 = 0; k0 < INW; k0 += 16) {
        float4 a0 = *(const float4*)&A[(size_t)(m0 + lr) * INW + k0 + lc];
        float4 a1 = *(const float4*)&A[(size_t)(m0 + lr) * INW + k0 + lc + 4];
        float4 b0 = *(const float4*)&W[(size_t)(n0 + lr) * INW + k0 + lc];
        float4 b1 = *(const float4*)&W[(size_t)(n0 + lr) * INW + k0 + lc + 4];
        As[lc + 0][lr] = a0.x; As[lc + 1][lr] = a0.y; As[lc + 2][lr] = a0.z; As[lc + 3][lr] = a0.w;
        As[lc + 4][lr] = a1.x; As[lc + 5][lr] = a1.y; As[lc + 6][lr] = a1.z; As[lc + 7][lr] = a1.w;
        Bs[lc + 0][lr] = b0.x; Bs[lc + 1][lr] = b0.y; Bs[lc + 2][lr] = b0.z; Bs[lc + 3][lr] = b0.w;
        Bs[lc + 4][lr] = b1.x; Bs[lc + 5][lr] = b1.y; Bs[lc + 6][lr] = b1.z; Bs[lc + 7][lr] = b1.w;
        __syncthreads();
#pragma unroll
        for (int kk = 0; kk < 16; kk++) {
            float4 x0 = *(const float4*)&As[kk][tm << 3];
            float4 x1 = *(const float4*)&As[kk][(tm << 3) + 4];
            float4 y0 = *(const float4*)&Bs[kk][tn << 3];
            float4 y1 = *(const float4*)&Bs[kk][(tn << 3) + 4];
            unsigned long long bb[4] = {pack2(y0.x, y0.y), pack2(y0.z, y0.w),
                                        pack2(y1.x, y1.y), pack2(y1.z, y1.w)};
            float av[8] = {x0.x, x0.y, x0.z, x0.w, x1.x, x1.y, x1.z, x1.w};
#pragma unroll
            for (int i = 0; i < 8; i++) {
                unsigned long long ad = pack2(av[i], av[i]);
#pragma unroll
                for (int j = 0; j < 4; j++) accp[i][j] = ffma2(ad, bb[j], accp[i][j]);
            }
        }
        __syncthreads();
    }
#pragma unroll
    for (int i = 0; i < 8; i++) {
        int m = m0 + (tm << 3) + i;
        int s = m >> 4, b = m & 15;
#pragma unroll
        for (int j = 0; j < 4; j++) {
            float2 u = unpack2(accp[i][j]);
            int n = n0 + (tn << 3) + (j << 1);
            int d0 = n >> 10, g0 = n & 1023;
            g_xproj[(size_t)((((d0 << 8) | s) << 10) | g0) * BATCH + b] = u.x + bias[n];
            int n1 = n + 1;
            int d1 = n1 >> 10, g1 = n1 & 1023;
            g_xproj[(size_t)((((d1 << 8) | s) << 10) | g1) * BATCH + b] = u.y + bias[n1];
        }
    }
}

// ---------------- 3) LSTM recurrence: cluster(8) + DSMEM h exchange ----------
// CTA = (dir bx>>6, bgroup (bx>>3)&7 [2 batches], rank bx&7 [32 units]).
// Cluster = 8 CTAs of one (dir,bgroup). Weights register-resident.
// h pushed into all 8 peers' smem via st.shared::cluster; sync = 1 mbarrier.
__global__ __launch_bounds__(256) __cluster_dims__(8, 1, 1)
void lstm_rec_kernel(int layer, const float* __restrict__ whh) {
    float* __restrict__ xout = layer ? g_xa : g_xb;
    int bx  = blockIdx.x;
    int dir = bx >> 6;
    int bgp = (bx >> 3) & 7;           // batches b0 = bgp*2, +1
    int rk  = bx & 7;                  // unit group: units j0..j0+31
    int j0  = rk << 5;
    int b0  = bgp << 1;
    int tid = threadIdx.x;
    int ks  = tid >> 5;                // k-slice 0..7 (32 k each)
    int un  = tid & 31;                // unit within group

    __shared__ __align__(16) float h_buf[2][512];     // [buf][b*256 + unit]
    __shared__ __align__(16) float part_s[8][264];    // [ks][gate g]
    __shared__ __align__(16) float gate_s[256];       // g = q*64 + u*2 + b
    __shared__ __align__(16) float hstage[64];        // [b*32 + u]
    __shared__ __align__(8)  unsigned long long mbar_store;

    unsigned sm_h    = smem_u32(&h_buf[0][0]);
    unsigned sm_mbar = smem_u32(&mbar_store);

    // weights: rows (q, unit j0+un), cols ks*32..+31 -> 16 f32x2 per gate
    unsigned long long w_ull[4][16];
#pragma unroll
    for (int q = 0; q < 4; q++) {
        const float* wr = whh + (size_t)((dir << 10) + (q << 8) + j0 + un) * HID + (ks << 5);
#pragma unroll
        for (int m = 0; m < 8; m++) {
            float4 f = *(const float4*)&wr[m << 2];
            w_ull[q][m * 2]     = pack2(f.x, f.y);
            w_ull[q][m * 2 + 1] = pack2(f.z, f.w);
        }
    }
    // init: h(0) = 0, barrier count = 16 (2 publisher threads x 8 CTAs)
    if (tid < 128) *(float4*)&h_buf[0][tid << 2] = make_float4(0.f, 0.f, 0.f, 0.f);
    if (tid == 0) mbar_init(sm_mbar, 16u);
    __syncthreads();
    asm volatile("barrier.cluster.arrive.aligned;" ::: "memory");
    asm volatile("barrier.cluster.wait.aligned;"   ::: "memory");

    float c_reg = 0.f;                 // act threads tid<64: u = tid>>1, b = tid&1
    // reduce/xp mapping: thread t -> gate (q = t>>6, u = (t&63)>>1, b = t&1)
    int rd_q = tid >> 6, rd_u = (tid & 63) >> 1, rd_b = tid & 1;
    int xp_base = (dir << 22) + ((rd_q << 8) + j0 + rd_u) * BATCH + b0 + rd_b;

    for (int p = 0; p < SQ; p++) {
        int t = dir ? (SQ - 1 - p) : p;
        float xp = __ldg(&g_xproj[xp_base + (t << 14)]);
        if (p > 0) mbar_wait(sm_mbar, (unsigned)((p - 1) & 1));

        // compute: 4 gates x 2 batches x 32 k per thread (broadcast LDS)
        const float* hcur = &h_buf[p & 1][0];
        unsigned long long acc[4][2];
#pragma unroll
        for (int q = 0; q < 4; q++) { acc[q][0] = 0ull; acc[q][1] = 0ull; }
#pragma unroll
        for (int b = 0; b < 2; b++) {
            const float* hb = hcur + (b << 8) + (ks << 5);
#pragma unroll
            for (int m = 0; m < 8; m++) {
                float4 h4 = *(const float4*)&hb[m << 2];
                unsigned long long h01 = pack2(h4.x, h4.y);
                unsigned long long h23 = pack2(h4.z, h4.w);
#pragma unroll
                for (int q = 0; q < 4; q++) {
                    acc[q][b] = ffma2(w_ull[q][m * 2],     h01, acc[q][b]);
                    acc[q][b] = ffma2(w_ull[q][m * 2 + 1], h23, acc[q][b]);
                }
            }
        }
        // partials: float2 per (q): [g = q*64 + un*2 + b]
#pragma unroll
        for (int q = 0; q < 4; q++) {
            float2 s0 = unpack2(acc[q][0]);
            float2 s1 = unpack2(acc[q][1]);
            *(float2*)&part_s[ks][(q << 6) + (un << 1)] =
                make_float2(s0.x + s0.y, s1.x + s1.y);
        }
        __syncthreads();

        // reduce 8 k-slices: thread t owns gate t
        float gsum = xp;
#pragma unroll
        for (int s2 = 0; s2 < 8; s2++) gsum += part_s[s2][tid];
        gate_s[tid] = gsum;
        __syncthreads();

        // activations: 64 threads, u = tid>>1, b = tid&1
        if (tid < 64) {
            float gi = gate_s[tid];
            float gf = gate_s[64 + tid];
            float gg = gate_s[128 + tid];
            float go = gate_s[192 + tid];
            c_reg = fsig(gf) * c_reg + fsig(gi) * ftanh(gg);
            float h = fsig(go) * ftanh(c_reg);
            int u = tid >> 1, b = tid & 1;
            hstage[(b << 5) + u] = h;
            xout[(size_t)((t * BATCH + b0 + b) << 9) + (dir << 8) + j0 + u] = h;
        }
        __syncthreads();

        // publish h(p+1) to all 8 CTAs' h_buf[(p+1)&1] (skip on last step)
        if (p + 1 < SQ && tid < 16) {
            unsigned dst = (unsigned)(tid >> 1);   // dest rank
            int b = tid & 1;
            // dest offset: buf*(2048B) + b*1024B + j0*4B
            unsigned off = sm_h + (((p + 1) & 1) << 11) + (b << 10) + (j0 << 2);
            unsigned ra = mapa_u32(off, dst);
            const float4* src = (const float4*)&hstage[b << 5];
#pragma unroll
            for (int i = 0; i < 8; i++) st_cluster_v4(ra + (i << 4), src[i]);
            mbar_arrive_rank(sm_mbar, dst);
        }
    }
    asm volatile("barrier.cluster.arrive.aligned;" ::: "memory");
    asm volatile("barrier.cluster.wait.aligned;"   ::: "memory");
}

// ---------------- 4) attention projections ----------------------------------
// n0 in {0,64} -> Ua -> g_p[(b*256+s)*128+n] ; n0 in {128,192} -> Wa -> g_cq
__global__ __launch_bounds__(256) void attnproj_kernel(const float* __restrict__ Ua,
                                                       const float* __restrict__ Wa) {
    const float* __restrict__ A = g_xa;   // layer-1 output [s][b][512]
    __shared__ __align__(16) float As[16][68];
    __shared__ __align__(16) float Bs[16][68];
    int m0 = blockIdx.y << 6;
    int n0 = blockIdx.x << 6;
    const float* Wsel = (n0 < 128) ? Ua : Wa;
    int nbase = (n0 < 128) ? n0 : (n0 - 128);
    float* out = (n0 < 128) ? g_p : g_cq;

    int tid = threadIdx.x;
    int tm = tid >> 4, tn = tid & 15;
    int lr = tid >> 2, lc = (tid & 3) << 2;

    unsigned long long accp[4][2];
#pragma unroll
    for (int i = 0; i < 4; i++) { accp[i][0] = 0ull; accp[i][1] = 0ull; }

    for (int k0 = 0; k0 < INW; k0 += 16) {
        float4 av = *(const float4*)&A[(size_t)(m0 + lr) * INW + k0 + lc];
        float4 bv = *(const float4*)&Wsel[(size_t)(nbase + lr) * INW + k0 + lc];
        As[lc + 0][lr] = av.x; As[lc + 1][lr] = av.y; As[lc + 2][lr] = av.z; As[lc + 3][lr] = av.w;
        Bs[lc + 0][lr] = bv.x; Bs[lc + 1][lr] = bv.y; Bs[lc + 2][lr] = bv.z; Bs[lc + 3][lr] = bv.w;
        __syncthreads();
#pragma unroll
        for (int kk = 0; kk < 16; kk++) {
            float4 a4 = *(const float4*)&As[kk][tm << 2];
            ulonglong2 b2 = *(const ulonglong2*)&Bs[kk][tn << 2];
            unsigned long long ad0 = pack2(a4.x, a4.x);
            unsigned long long ad1 = pack2(a4.y, a4.y);
            unsigned long long ad2 = pack2(a4.z, a4.z);
            unsigned long long ad3 = pack2(a4.w, a4.w);
            accp[0][0] = ffma2(ad0, b2.x, accp[0][0]);
            accp[0][1] = ffma2(ad0, b2.y, accp[0][1]);
            accp[1][0] = ffma2(ad1, b2.x, accp[1][0]);
            accp[1][1] = ffma2(ad1, b2.y, accp[1][1]);
            accp[2][0] = ffma2(ad2, b2.x, accp[2][0]);
            accp[2][1] = ffma2(ad2, b2.y, accp[2][1]);
            accp[3][0] = ffma2(ad3, b2.x, accp[3][0]);
            accp[3][1] = ffma2(ad3, b2.y, accp[3][1]);
        }
        __syncthreads();
    }
#pragma unroll
    for (int i = 0; i < 4; i++) {
        int m = m0 + (tm << 2) + i;
        int s = m >> 4, b = m & 15;
        float2 u0 = unpack2(accp[i][0]);
        float2 u1 = unpack2(accp[i][1]);
        float vals[4] = {u0.x, u0.y, u1.x, u1.y};
#pragma unroll
        for (int j = 0; j < 4; j++) {
            int nl = nbase + (tn << 2) + j;
            out[(size_t)(((b << 8) + s) << 7) + nl] = vals[j];
        }
    }
}

// ---------------- 5) pairwise scores + predictions --------------------------
// scores[b,i,j] = sum_h va[h]*tanh(p[b,i,h]+c[b,j,h]);  pred = (score >= 0)
__global__ __launch_bounds__(256) void scores_kernel(const float* __restrict__ va,
                                                     float* __restrict__ out,
                                                     int write_pred) {
    __shared__ __align__(16) float ps[32][132];
    __shared__ __align__(16) float cs[32][132];
    __shared__ float va_s[HMD];
    int b  = blockIdx.z;
    int i0 = blockIdx.y << 5, j0 = blockIdx.x << 5;
    int tid = threadIdx.x;
    if (tid < HMD) va_s[tid] = va[tid];
#pragma unroll
    for (int i = 0; i < 4; i++) {
        int f4 = tid + (i << 8);                 // 1024 float4s total
        int row = f4 >> 5;
        int col = (f4 & 31) << 2;
        *(float4*)&ps[row][col] =
            *(const float4*)&g_p[(size_t)(((b << 8) + i0 + row) << 7) + col];
        *(float4*)&cs[row][col] =
            *(const float4*)&g_cq[(size_t)(((b << 8) + j0 + row) << 7) + col];
    }
    __syncthreads();

    int tj = tid & 15, ti = tid >> 4;
    int ia = ti << 1, ja = tj << 1;
    float s00 = 0.f, s01 = 0.f, s10 = 0.f, s11 = 0.f;
#pragma unroll 4
    for (int h = 0; h < HMD; h++) {
        float v  = va_s[h];
        float pa = ps[ia][h],     pb = ps[ia + 1][h];
        float ca = cs[ja][h],     cb = cs[ja + 1][h];
        s00 += v * ftanh(pa + ca);
        s01 += v * ftanh(pa + cb);
        s10 += v * ftanh(pb + ca);
        s11 += v * ftanh(pb + cb);
    }
    int gi = i0 + ia, gj = j0 + ja;
    size_t base = ((size_t)b << 16) + ((size_t)gi << 8) + gj;
    out[base]           = s00;
    out[base + 1]       = s01;
    out[base + 256]     = s10;
    out[base + 257]     = s11;
    if (write_pred) {
        float* po = out + NSC;
        po[base]       = (s00 >= 0.f) ? 1.f : 0.f;
        po[base + 1]   = (s01 >= 0.f) ? 1.f : 0.f;
        po[base + 256] = (s10 >= 0.f) ? 1.f : 0.f;
        po[base + 257] = (s11 >= 0.f) ? 1.f : 0.f;
    }
}

// ---------------- launch -----------------------------------------------------
extern "C" void kernel_launch(void* const* d_in, const int* in_sizes, int n_in,
                              void* d_out, int out_size) {
    const int*   concepts = (const int*)d_in[0];
    // d_in[1] = concepts_lengths (all full-length; unused)
    const float* emb  = (const float*)d_in[2];
    const float* w_ih = (const float*)d_in[3];
    const float* w_hh = (const float*)d_in[4];
    const float* bias = (const float*)d_in[5];
    const float* Ua   = (const float*)d_in[6];
    const float* Wa   = (const float*)d_in[7];
    const float* va   = (const float*)d_in[8];
    float* out = (float*)d_out;

    embed_kernel<<<NROWS, 128>>>(concepts, emb);

    // layer 0
    inproj_kernel<<<dim3(16, 32), 256>>>(0, w_ih, bias);
    lstm_rec_kernel<<<128, 256>>>(0, w_hh);
    // layer 1
    inproj_kernel<<<dim3(16, 32), 256>>>(1, w_ih + 2 * G4 * EMB, bias + 2 * G4);
    lstm_rec_kernel<<<128, 256>>>(1, w_hh + 2 * G4 * HID);

    attnproj_kernel<<<dim3(4, 64), 256>>>(Ua, Wa);

    int write_pred = (out_size >= 2 * NSC) ? 1 : 0;
    scores_kernel<<<dim3(8, 8, BATCH), 256>>>(va, out, write_pred);
}